// round 4
// baseline (speedup 1.0000x reference)
#include <cuda_runtime.h>
#include <cstdint>
#include <cstddef>

#define BATCH 32
#define NQ    1024
#define LSEQ  512
#define DIM   768

// Scratch (device globals)
__device__ float g_rq [(size_t)BATCH * NQ   * DIM ];  // tf32-rounded q
__device__ float g_rk [(size_t)BATCH * LSEQ * DIM ];  // tf32-rounded k
__device__ float g_rv [(size_t)BATCH * LSEQ * DIM ];  // tf32-rounded v
__device__ float g_rw [3 * DIM * DIM];                // tf32-rounded q_w,k_w,v_w
__device__ float g_qp [(size_t)BATCH * NQ   * DIM ];  // qp  [b][n][d] (tf32-rounded)
__device__ float g_kp [(size_t)BATCH * LSEQ * DIM ];  // kp  [b][l][d] (tf32-rounded)
__device__ float g_vpt[(size_t)BATCH * DIM  * LSEQ];  // vpT [b][d][l] (tf32-rounded)
__device__ float g_s  [(size_t)BATCH * NQ   * LSEQ];  // S/P [b][n][l]

__device__ __forceinline__ float tf32r(float x) {
    unsigned r; asm("cvt.rna.tf32.f32 %0,%1;" : "=r"(r) : "f"(x));
    return __uint_as_float(r);
}

__device__ __forceinline__ void mma_tf32(float c[4],
    unsigned a0, unsigned a1, unsigned a2, unsigned a3,
    unsigned b0, unsigned b1)
{
    asm("mma.sync.aligned.m16n8k8.row.col.f32.tf32.tf32.f32 "
        "{%0,%1,%2,%3},{%4,%5,%6,%7},{%8,%9},{%0,%1,%2,%3};"
        : "+f"(c[0]), "+f"(c[1]), "+f"(c[2]), "+f"(c[3])
        : "r"(a0), "r"(a1), "r"(a2), "r"(a3), "r"(b0), "r"(b1));
}

__device__ __forceinline__ void cp16(uint32_t dst, const void* src) {
    asm volatile("cp.async.cg.shared.global [%0], [%1], 16;" :: "r"(dst), "l"(src));
}
#define CP_COMMIT() asm volatile("cp.async.commit_group;" ::: "memory")
#define CP_WAIT2()  asm volatile("cp.async.wait_group 2;" ::: "memory")
#define CP_WAIT0()  asm volatile("cp.async.wait_group 0;" ::: "memory")

__device__ __forceinline__ uint32_t s2u(const void* p) {
    uint32_t a;
    asm("{ .reg .u64 t; cvta.to.shared.u64 t, %1; cvt.u32.u64 %0, t; }"
        : "=r"(a) : "l"(p));
    return a;
}

// ---------------------------------------------------------------------------
// Elementwise tf32 rounding: dst[i] = round_tf32(src[i])
// ---------------------------------------------------------------------------
__global__ __launch_bounds__(256) void round_tf32(
    const float* __restrict__ src, float* __restrict__ dst, int n4)
{
    int i = blockIdx.x * 256 + threadIdx.x;
    if (i < n4) {
        float4 v = ((const float4*)src)[i];
        v.x = tf32r(v.x); v.y = tf32r(v.y); v.z = tf32r(v.z); v.w = tf32r(v.w);
        ((float4*)dst)[i] = v;
    }
}

// ---------------------------------------------------------------------------
// C[M,N] = A[M,K] @ B[N,K]^T (+bias). A,B row-major, K-contiguous, tf32-exact.
// Block 128(M) x 256(N) x 32(K). 256 threads, warp grid 2x4, warp tile 64x64.
// Smem row stride 36 floats; cp.async 3-stage ring.
// biasMode: 0 none, 1 col bias[n], 2 row bias[m].  roundOut: tf32-round stores.
// ---------------------------------------------------------------------------
#define RS      36                    // smem row stride (floats)
#define A_STAGE (128 * RS * 4)        // 18432 B
#define B_STAGE (256 * RS * 4)        // 36864 B
#define STAGE   (A_STAGE + B_STAGE)   // 55296 B
#define SMEM_BYTES (3 * STAGE)        // 165888 B

__global__ __launch_bounds__(256) void tgemm_nt(
    const float* __restrict__ A, const float* __restrict__ Bm,
    const float* __restrict__ bias, float* __restrict__ C,
    int K, int Ntot, long sA, long sB, long sC, int biasMode, int roundOut)
{
    extern __shared__ char smem[];
    const uint32_t sb = s2u(smem);

    const int tid  = threadIdx.x;
    const int lane = tid & 31;
    const int wid  = tid >> 5;
    const int wm   = (wid >> 2) * 64;   // warp m offset (0,64)
    const int wn   = (wid & 3) * 64;    // warp n offset (0,64,128,192)
    const int gid  = lane >> 2;         // 0..7
    const int tig  = lane & 3;          // 0..3

    const float* Ab = A  + (size_t)blockIdx.z * sA + (size_t)blockIdx.y * 128 * K;
    const float* Bb = Bm + (size_t)blockIdx.z * sB + (size_t)blockIdx.x * 256 * K;
    float*       Cb = C  + (size_t)blockIdx.z * sC;

    const int arow = tid >> 1;          // 0..127
    const int ahalf = (tid & 1) * 16;   // 0 or 16 (floats)

    const int nkt = K / 32;

    // ---- async tile issue ----
    auto issue = [&](int t) {
        const int s = t % 3;
        const uint32_t As = sb + s * STAGE;
        const uint32_t Bs = As + A_STAGE;
        const float* ga = Ab + (size_t)arow * K + t * 32 + ahalf;
        #pragma unroll
        for (int i = 0; i < 4; i++)
            cp16(As + (uint32_t)arow * (RS * 4) + (ahalf + i * 4) * 4, ga + i * 4);
        const float* gb = Bb + (size_t)tid * K + t * 32;
        #pragma unroll
        for (int i = 0; i < 8; i++)
            cp16(Bs + (uint32_t)tid * (RS * 4) + i * 16, gb + i * 4);
        CP_COMMIT();
    };

    issue(0); issue(1); issue(2);

    float acc[4][8][4];
    #pragma unroll
    for (int mi = 0; mi < 4; mi++)
        #pragma unroll
        for (int nj = 0; nj < 8; nj++)
            #pragma unroll
            for (int r = 0; r < 4; r++) acc[mi][nj][r] = 0.f;

    for (int t = 0; t < nkt; t++) {
        const int s = t % 3;
        const uint32_t As = sb + s * STAGE;
        const uint32_t Bs = As + A_STAGE;

        CP_WAIT2();
        __syncthreads();

        #pragma unroll
        for (int kk = 0; kk < 4; kk++) {
            const int kb = kk * 8;
            unsigned a[4][4], b[8][2];
            #pragma unroll
            for (int mi = 0; mi < 4; mi++) {
                const uint32_t base = As + (((uint32_t)(wm + mi * 16 + gid)) * RS + kb + tig) * 4;
                asm volatile("ld.shared.b32 %0, [%1];"      : "=r"(a[mi][0]) : "r"(base));
                asm volatile("ld.shared.b32 %0, [%1+1152];" : "=r"(a[mi][1]) : "r"(base)); // +8 rows
                asm volatile("ld.shared.b32 %0, [%1+16];"   : "=r"(a[mi][2]) : "r"(base)); // +4 k
                asm volatile("ld.shared.b32 %0, [%1+1168];" : "=r"(a[mi][3]) : "r"(base));
            }
            #pragma unroll
            for (int nj = 0; nj < 8; nj++) {
                const uint32_t base = Bs + (((uint32_t)(wn + nj * 8 + gid)) * RS + kb + tig) * 4;
                asm volatile("ld.shared.b32 %0, [%1];"    : "=r"(b[nj][0]) : "r"(base));
                asm volatile("ld.shared.b32 %0, [%1+16];" : "=r"(b[nj][1]) : "r"(base));
            }
            #pragma unroll
            for (int mi = 0; mi < 4; mi++)
                #pragma unroll
                for (int nj = 0; nj < 8; nj++)
                    mma_tf32(acc[mi][nj], a[mi][0], a[mi][1], a[mi][2], a[mi][3],
                             b[nj][0], b[nj][1]);
        }

        __syncthreads();
        if (t + 3 < nkt) issue(t + 3);
    }
    CP_WAIT0();

    // ---- epilogue ----
    #pragma unroll
    for (int mi = 0; mi < 4; mi++) {
        const int row0 = blockIdx.y * 128 + wm + mi * 16 + gid;
        float rb0 = (biasMode == 2) ? __ldg(bias + row0)     : 0.f;
        float rb1 = (biasMode == 2) ? __ldg(bias + row0 + 8) : 0.f;
        #pragma unroll
        for (int nj = 0; nj < 8; nj++) {
            const int col = blockIdx.x * 256 + wn + nj * 8 + 2 * tig;
            float c0 = acc[mi][nj][0], c1 = acc[mi][nj][1];
            float c2 = acc[mi][nj][2], c3 = acc[mi][nj][3];
            if (biasMode == 1) {
                float b0 = __ldg(bias + col), b1 = __ldg(bias + col + 1);
                c0 += b0; c1 += b1; c2 += b0; c3 += b1;
            } else if (biasMode == 2) {
                c0 += rb0; c1 += rb0; c2 += rb1; c3 += rb1;
            }
            if (roundOut) {
                c0 = tf32r(c0); c1 = tf32r(c1); c2 = tf32r(c2); c3 = tf32r(c3);
            }
            *(float2*)(Cb + (size_t)row0 * Ntot + col)       = make_float2(c0, c1);
            *(float2*)(Cb + (size_t)(row0 + 8) * Ntot + col) = make_float2(c2, c3);
        }
    }
}

// ---------------------------------------------------------------------------
// In-place scaled softmax over rows of 512; outputs tf32-rounded.
// ---------------------------------------------------------------------------
__global__ __launch_bounds__(256) void softmax_rows(float* __restrict__ S, float scale)
{
    const int row  = blockIdx.x * 8 + (threadIdx.x >> 5);
    const int lane = threadIdx.x & 31;
    float4* r4 = (float4*)(S + (size_t)row * LSEQ) + lane;

    float4 v[4];
    #pragma unroll
    for (int i = 0; i < 4; i++) {
        v[i] = r4[32 * i];
        v[i].x *= scale; v[i].y *= scale; v[i].z *= scale; v[i].w *= scale;
    }
    float mx = -3.4e38f;
    #pragma unroll
    for (int i = 0; i < 4; i++)
        mx = fmaxf(mx, fmaxf(fmaxf(v[i].x, v[i].y), fmaxf(v[i].z, v[i].w)));
    #pragma unroll
    for (int o = 16; o > 0; o >>= 1)
        mx = fmaxf(mx, __shfl_xor_sync(0xffffffffu, mx, o));
    float sum = 0.f;
    #pragma unroll
    for (int i = 0; i < 4; i++) {
        v[i].x = __expf(v[i].x - mx); v[i].y = __expf(v[i].y - mx);
        v[i].z = __expf(v[i].z - mx); v[i].w = __expf(v[i].w - mx);
        sum += v[i].x + v[i].y + v[i].z + v[i].w;
    }
    #pragma unroll
    for (int o = 16; o > 0; o >>= 1)
        sum += __shfl_xor_sync(0xffffffffu, sum, o);
    const float inv = 1.0f / sum;
    #pragma unroll
    for (int i = 0; i < 4; i++) {
        v[i].x = tf32r(v[i].x * inv); v[i].y = tf32r(v[i].y * inv);
        v[i].z = tf32r(v[i].z * inv); v[i].w = tf32r(v[i].w * inv);
        r4[32 * i] = v[i];
    }
}

extern "C" void kernel_launch(void* const* d_in, const int* in_sizes, int n_in,
                              void* d_out, int out_size)
{
    const float* q   = (const float*)d_in[0];
    const float* k   = (const float*)d_in[1];
    const float* v   = (const float*)d_in[2];
    const float* q_w = (const float*)d_in[3];
    const float* q_b = (const float*)d_in[4];
    const float* k_w = (const float*)d_in[5];
    const float* k_b = (const float*)d_in[6];
    const float* v_w = (const float*)d_in[7];
    const float* v_b = (const float*)d_in[8];
    float* out = (float*)d_out;

    float *rq, *rk, *rv, *rw, *qp, *kp, *vpt, *s;
    cudaGetSymbolAddress((void**)&rq,  g_rq);
    cudaGetSymbolAddress((void**)&rk,  g_rk);
    cudaGetSymbolAddress((void**)&rv,  g_rv);
    cudaGetSymbolAddress((void**)&rw,  g_rw);
    cudaGetSymbolAddress((void**)&qp,  g_qp);
    cudaGetSymbolAddress((void**)&kp,  g_kp);
    cudaGetSymbolAddress((void**)&vpt, g_vpt);
    cudaGetSymbolAddress((void**)&s,   g_s);

    cudaFuncSetAttribute(tgemm_nt, cudaFuncAttributeMaxDynamicSharedMemorySize, SMEM_BYTES);

    // tf32-round inputs
    const int nq4 = BATCH * NQ * DIM / 4, nk4 = BATCH * LSEQ * DIM / 4, nw4 = DIM * DIM / 4;
    round_tf32<<<(nq4 + 255) / 256, 256>>>(q, rq, nq4);
    round_tf32<<<(nk4 + 255) / 256, 256>>>(k, rk, nk4);
    round_tf32<<<(nk4 + 255) / 256, 256>>>(v, rv, nk4);
    round_tf32<<<(nw4 + 255) / 256, 256>>>(q_w, rw,            nw4);
    round_tf32<<<(nw4 + 255) / 256, 256>>>(k_w, rw + nw4 * 4,     nw4);
    round_tf32<<<(nw4 + 255) / 256, 256>>>(v_w, rw + 2 * nw4 * 4, nw4);

    // qp = rq @ qw^T + qb   (M=32768, N=768)
    tgemm_nt<<<dim3(DIM / 256, (BATCH * NQ) / 128, 1), 256, SMEM_BYTES>>>(
        rq, rw, q_b, qp, DIM, DIM, 0, 0, 0, 1, 1);
    // kp = rk @ kw^T + kb   (M=16384, N=768)
    tgemm_nt<<<dim3(DIM / 256, (BATCH * LSEQ) / 128, 1), 256, SMEM_BYTES>>>(
        rk, rw + (size_t)DIM * DIM, k_b, kp, DIM, DIM, 0, 0, 0, 1, 1);
    // vpT[b,d,l] = vw @ rv[b]^T + vb[d]  (per batch: M=768, N=512, row bias)
    tgemm_nt<<<dim3(LSEQ / 256, DIM / 128, BATCH), 256, SMEM_BYTES>>>(
        rw + 2 * (size_t)DIM * DIM, rv, v_b, vpt, DIM, LSEQ,
        0, (long)LSEQ * DIM, (long)DIM * LSEQ, 2, 1);
    // S[b] = qp[b] @ kp[b]^T   (per batch: M=1024, N=512)
    tgemm_nt<<<dim3(LSEQ / 256, NQ / 128, BATCH), 256, SMEM_BYTES>>>(
        qp, kp, nullptr, s, DIM, LSEQ,
        (long)NQ * DIM, (long)LSEQ * DIM, (long)NQ * LSEQ, 0, 0);
    // softmax (rounds output to tf32)
    softmax_rows<<<(BATCH * NQ) / 8, 256>>>(s, 0.03608439182435161f);
    // out[b] = P[b] @ vpT[b]^T   (per batch: M=1024, N=768)
    tgemm_nt<<<dim3(DIM / 256, NQ / 128, BATCH), 256, SMEM_BYTES>>>(
        s, vpt, nullptr, out, LSEQ, DIM,
        (long)NQ * LSEQ, (long)DIM * LSEQ, (long)NQ * DIM, 0, 0);
}

// round 5
// speedup vs baseline: 1.3520x; 1.3520x over previous
#include <cuda_runtime.h>
#include <cstdint>
#include <cstddef>

#define BATCH 32
#define NQ    1024
#define LSEQ  512
#define DIM   768

// Scratch (device globals)
__device__ float g_rq [(size_t)BATCH * NQ   * DIM ];  // tf32-rounded q
__device__ float g_rk [(size_t)BATCH * LSEQ * DIM ];  // tf32-rounded k
__device__ float g_rv [(size_t)BATCH * LSEQ * DIM ];  // tf32-rounded v
__device__ float g_rw [3 * DIM * DIM];                // tf32-rounded q_w,k_w,v_w
__device__ float g_qp [(size_t)BATCH * NQ   * DIM ];  // qp  [b][n][d]
__device__ float g_kp [(size_t)BATCH * LSEQ * DIM ];  // kp  [b][l][d]
__device__ float g_vpt[(size_t)BATCH * DIM  * LSEQ];  // vpT [b][d][l]
__device__ float g_s  [(size_t)BATCH * NQ   * LSEQ];  // S/P [b][n][l]

__device__ __forceinline__ float tf32r(float x) {
    unsigned r; asm("cvt.rna.tf32.f32 %0,%1;" : "=r"(r) : "f"(x));
    return __uint_as_float(r);
}

__device__ __forceinline__ void mma_tf32(float c[4],
    unsigned a0, unsigned a1, unsigned a2, unsigned a3,
    unsigned b0, unsigned b1)
{
    asm("mma.sync.aligned.m16n8k8.row.col.f32.tf32.tf32.f32 "
        "{%0,%1,%2,%3},{%4,%5,%6,%7},{%8,%9},{%0,%1,%2,%3};"
        : "+f"(c[0]), "+f"(c[1]), "+f"(c[2]), "+f"(c[3])
        : "r"(a0), "r"(a1), "r"(a2), "r"(a3), "r"(b0), "r"(b1));
}

__device__ __forceinline__ void ldsm_x4(unsigned r[4], uint32_t addr) {
    asm volatile("ldmatrix.sync.aligned.m8n8.x4.shared.b16 {%0,%1,%2,%3}, [%4];"
        : "=r"(r[0]), "=r"(r[1]), "=r"(r[2]), "=r"(r[3]) : "r"(addr));
}
__device__ __forceinline__ void ldsm_x2(unsigned r[2], uint32_t addr) {
    asm volatile("ldmatrix.sync.aligned.m8n8.x2.shared.b16 {%0,%1}, [%2];"
        : "=r"(r[0]), "=r"(r[1]) : "r"(addr));
}

__device__ __forceinline__ void cp16(uint32_t dst, const void* src) {
    asm volatile("cp.async.cg.shared.global [%0], [%1], 16;" :: "r"(dst), "l"(src));
}
#define CP_COMMIT() asm volatile("cp.async.commit_group;" ::: "memory")
#define CP_WAIT2()  asm volatile("cp.async.wait_group 2;" ::: "memory")
#define CP_WAIT0()  asm volatile("cp.async.wait_group 0;" ::: "memory")

__device__ __forceinline__ uint32_t s2u(const void* p) {
    uint32_t a;
    asm("{ .reg .u64 t; cvta.to.shared.u64 t, %1; cvt.u32.u64 %0, t; }"
        : "=r"(a) : "l"(p));
    return a;
}

// ---------------------------------------------------------------------------
// Elementwise tf32 rounding
// ---------------------------------------------------------------------------
__global__ __launch_bounds__(256) void round_tf32(
    const float* __restrict__ src, float* __restrict__ dst, int n4)
{
    int i = blockIdx.x * 256 + threadIdx.x;
    if (i < n4) {
        float4 v = ((const float4*)src)[i];
        v.x = tf32r(v.x); v.y = tf32r(v.y); v.z = tf32r(v.z); v.w = tf32r(v.w);
        ((float4*)dst)[i] = v;
    }
}

// ---------------------------------------------------------------------------
// C[M,N] = A[M,K] @ B[N,K]^T (+bias). A,B row-major K-contiguous, tf32-exact.
// Block 128x128x32. 256 thr, warp grid 2x4, warp tile 64x32.
// Tiles in smem: [row][8 chunks of 16B], chunk XOR-swizzled by (row&7).
// cp.async 3-stage ring; ldmatrix fragment loads.
// biasMode: 0 none, 1 col bias[n], 2 row bias[m]. roundOut: tf32-round stores.
// ---------------------------------------------------------------------------
#define TILE_B  16384                 // 128 rows * 128 bytes
#define STAGE   (2 * TILE_B)          // 32768
#define SMEM_BYTES (3 * STAGE)        // 98304

__global__ __launch_bounds__(256, 2) void tgemm_nt(
    const float* __restrict__ A, const float* __restrict__ Bm,
    const float* __restrict__ bias, float* __restrict__ C,
    int K, int Ntot, long sA, long sB, long sC, int biasMode, int roundOut)
{
    extern __shared__ char smem[];
    const uint32_t sb = s2u(smem);

    const int tid  = threadIdx.x;
    const int lane = tid & 31;
    const int wid  = tid >> 5;
    const int wm   = (wid >> 2) * 64;   // warp m offset (0,64)
    const int wn   = (wid & 3) * 32;    // warp n offset (0,32,64,96)
    const int gid  = lane >> 2;         // 0..7
    const int tig  = lane & 3;          // 0..3

    const float* Ab = A  + (size_t)blockIdx.z * sA + (size_t)blockIdx.y * 128 * K;
    const float* Bb = Bm + (size_t)blockIdx.z * sB + (size_t)blockIdx.x * 128 * K;
    float*       Cb = C  + (size_t)blockIdx.z * sC;

    const int crow  = tid >> 1;          // 0..127 (copy row)
    const int cbase = (tid & 1) * 4;     // chunk base 0 or 4
    const int nkt   = K / 32;

    auto issue = [&](int t) {
        const int s = t % 3;
        const uint32_t As = sb + s * STAGE;
        const uint32_t Bs = As + TILE_B;
        const float* ga = Ab + (size_t)crow * K + t * 32 + cbase * 4;
        const float* gb = Bb + (size_t)crow * K + t * 32 + cbase * 4;
        const uint32_t arow = As + (uint32_t)crow * 128;
        const uint32_t brow = Bs + (uint32_t)crow * 128;
        const int r7 = crow & 7;
        #pragma unroll
        for (int i = 0; i < 4; i++) {
            const uint32_t off = (uint32_t)(((cbase + i) ^ r7) * 16);
            cp16(arow + off, ga + i * 4);
            cp16(brow + off, gb + i * 4);
        }
        CP_COMMIT();
    };

    issue(0); issue(1); issue(2);

    float acc[4][4][4];
    #pragma unroll
    for (int mi = 0; mi < 4; mi++)
        #pragma unroll
        for (int nj = 0; nj < 4; nj++)
            #pragma unroll
            for (int r = 0; r < 4; r++) acc[mi][nj][r] = 0.f;

    // ldmatrix lane-address components (row fixed per thread)
    const int la15 = lane & 15;          // A: row within 16-row fragment
    const int lahi = lane >> 4;          // A: chunk +0/+1
    const int lb7  = lane & 7;           // B: row within 8-row fragment
    const int lbhi = (lane >> 3) & 1;    // B: chunk +0/+1

    for (int t = 0; t < nkt; t++) {
        const int s = t % 3;
        const uint32_t As = sb + s * STAGE;
        const uint32_t Bs = As + TILE_B;

        CP_WAIT2();
        __syncthreads();

        #pragma unroll
        for (int kk = 0; kk < 4; kk++) {
            unsigned a[4][4], b[4][2];
            #pragma unroll
            for (int mi = 0; mi < 4; mi++) {
                const int rowA = wm + mi * 16 + la15;
                const uint32_t addr = As + (uint32_t)rowA * 128
                    + (uint32_t)((((kk * 2) + lahi) ^ (rowA & 7)) * 16);
                ldsm_x4(a[mi], addr);
            }
            #pragma unroll
            for (int nj = 0; nj < 4; nj++) {
                const int rowB = wn + nj * 8 + lb7;
                const uint32_t addr = Bs + (uint32_t)rowB * 128
                    + (uint32_t)((((kk * 2) + lbhi) ^ (rowB & 7)) * 16);
                ldsm_x2(b[nj], addr);
            }
            #pragma unroll
            for (int mi = 0; mi < 4; mi++)
                #pragma unroll
                for (int nj = 0; nj < 4; nj++)
                    mma_tf32(acc[mi][nj], a[mi][0], a[mi][1], a[mi][2], a[mi][3],
                             b[nj][0], b[nj][1]);
        }

        __syncthreads();
        if (t + 3 < nkt) issue(t + 3);
    }
    CP_WAIT0();

    // ---- epilogue ----
    #pragma unroll
    for (int mi = 0; mi < 4; mi++) {
        const int row0 = blockIdx.y * 128 + wm + mi * 16 + gid;
        float rb0 = (biasMode == 2) ? __ldg(bias + row0)     : 0.f;
        float rb1 = (biasMode == 2) ? __ldg(bias + row0 + 8) : 0.f;
        #pragma unroll
        for (int nj = 0; nj < 4; nj++) {
            const int col = blockIdx.x * 128 + wn + nj * 8 + 2 * tig;
            float c0 = acc[mi][nj][0], c1 = acc[mi][nj][1];
            float c2 = acc[mi][nj][2], c3 = acc[mi][nj][3];
            if (biasMode == 1) {
                float b0 = __ldg(bias + col), b1 = __ldg(bias + col + 1);
                c0 += b0; c1 += b1; c2 += b0; c3 += b1;
            } else if (biasMode == 2) {
                c0 += rb0; c1 += rb0; c2 += rb1; c3 += rb1;
            }
            if (roundOut) {
                c0 = tf32r(c0); c1 = tf32r(c1); c2 = tf32r(c2); c3 = tf32r(c3);
            }
            *(float2*)(Cb + (size_t)row0 * Ntot + col)       = make_float2(c0, c1);
            *(float2*)(Cb + (size_t)(row0 + 8) * Ntot + col) = make_float2(c2, c3);
        }
    }
}

// ---------------------------------------------------------------------------
// In-place scaled softmax over rows of 512; outputs tf32-rounded.
// ---------------------------------------------------------------------------
__global__ __launch_bounds__(256) void softmax_rows(float* __restrict__ S, float scale)
{
    const int row  = blockIdx.x * 8 + (threadIdx.x >> 5);
    const int lane = threadIdx.x & 31;
    float4* r4 = (float4*)(S + (size_t)row * LSEQ) + lane;

    float4 v[4];
    #pragma unroll
    for (int i = 0; i < 4; i++) {
        v[i] = r4[32 * i];
        v[i].x *= scale; v[i].y *= scale; v[i].z *= scale; v[i].w *= scale;
    }
    float mx = -3.4e38f;
    #pragma unroll
    for (int i = 0; i < 4; i++)
        mx = fmaxf(mx, fmaxf(fmaxf(v[i].x, v[i].y), fmaxf(v[i].z, v[i].w)));
    #pragma unroll
    for (int o = 16; o > 0; o >>= 1)
        mx = fmaxf(mx, __shfl_xor_sync(0xffffffffu, mx, o));
    float sum = 0.f;
    #pragma unroll
    for (int i = 0; i < 4; i++) {
        v[i].x = __expf(v[i].x - mx); v[i].y = __expf(v[i].y - mx);
        v[i].z = __expf(v[i].z - mx); v[i].w = __expf(v[i].w - mx);
        sum += v[i].x + v[i].y + v[i].z + v[i].w;
    }
    #pragma unroll
    for (int o = 16; o > 0; o >>= 1)
        sum += __shfl_xor_sync(0xffffffffu, sum, o);
    const float inv = 1.0f / sum;
    #pragma unroll
    for (int i = 0; i < 4; i++) {
        v[i].x = tf32r(v[i].x * inv); v[i].y = tf32r(v[i].y * inv);
        v[i].z = tf32r(v[i].z * inv); v[i].w = tf32r(v[i].w * inv);
        r4[32 * i] = v[i];
    }
}

extern "C" void kernel_launch(void* const* d_in, const int* in_sizes, int n_in,
                              void* d_out, int out_size)
{
    const float* q   = (const float*)d_in[0];
    const float* k   = (const float*)d_in[1];
    const float* v   = (const float*)d_in[2];
    const float* q_w = (const float*)d_in[3];
    const float* q_b = (const float*)d_in[4];
    const float* k_w = (const float*)d_in[5];
    const float* k_b = (const float*)d_in[6];
    const float* v_w = (const float*)d_in[7];
    const float* v_b = (const float*)d_in[8];
    float* out = (float*)d_out;

    float *rq, *rk, *rv, *rw, *qp, *kp, *vpt, *s;
    cudaGetSymbolAddress((void**)&rq,  g_rq);
    cudaGetSymbolAddress((void**)&rk,  g_rk);
    cudaGetSymbolAddress((void**)&rv,  g_rv);
    cudaGetSymbolAddress((void**)&rw,  g_rw);
    cudaGetSymbolAddress((void**)&qp,  g_qp);
    cudaGetSymbolAddress((void**)&kp,  g_kp);
    cudaGetSymbolAddress((void**)&vpt, g_vpt);
    cudaGetSymbolAddress((void**)&s,   g_s);

    cudaFuncSetAttribute(tgemm_nt, cudaFuncAttributeMaxDynamicSharedMemorySize, SMEM_BYTES);

    // tf32-round inputs
    const int nq4 = BATCH * NQ * DIM / 4, nk4 = BATCH * LSEQ * DIM / 4, nw4 = DIM * DIM / 4;
    round_tf32<<<(nq4 + 255) / 256, 256>>>(q, rq, nq4);
    round_tf32<<<(nk4 + 255) / 256, 256>>>(k, rk, nk4);
    round_tf32<<<(nk4 + 255) / 256, 256>>>(v, rv, nk4);
    round_tf32<<<(nw4 + 255) / 256, 256>>>(q_w, rw,               nw4);
    round_tf32<<<(nw4 + 255) / 256, 256>>>(k_w, rw + nw4 * 4,     nw4);
    round_tf32<<<(nw4 + 255) / 256, 256>>>(v_w, rw + 2 * nw4 * 4, nw4);

    // qp = rq @ qw^T + qb   (M=32768, N=768)
    tgemm_nt<<<dim3(DIM / 128, (BATCH * NQ) / 128, 1), 256, SMEM_BYTES>>>(
        rq, rw, q_b, qp, DIM, DIM, 0, 0, 0, 1, 1);
    // kp = rk @ kw^T + kb   (M=16384, N=768)
    tgemm_nt<<<dim3(DIM / 128, (BATCH * LSEQ) / 128, 1), 256, SMEM_BYTES>>>(
        rk, rw + (size_t)DIM * DIM, k_b, kp, DIM, DIM, 0, 0, 0, 1, 1);
    // vpT[b,d,l] = vw @ rv[b]^T + vb[d]  (per batch: M=768, N=512, row bias)
    tgemm_nt<<<dim3(LSEQ / 128, DIM / 128, BATCH), 256, SMEM_BYTES>>>(
        rw + 2 * (size_t)DIM * DIM, rv, v_b, vpt, DIM, LSEQ,
        0, (long)LSEQ * DIM, (long)DIM * LSEQ, 2, 1);
    // S[b] = qp[b] @ kp[b]^T   (per batch: M=1024, N=512)
    tgemm_nt<<<dim3(LSEQ / 128, NQ / 128, BATCH), 256, SMEM_BYTES>>>(
        qp, kp, nullptr, s, DIM, LSEQ,
        (long)NQ * DIM, (long)LSEQ * DIM, (long)NQ * LSEQ, 0, 0);
    // softmax (rounds output to tf32)
    softmax_rows<<<(BATCH * NQ) / 8, 256>>>(s, 0.03608439182435161f);
    // out[b] = P[b] @ vpT[b]^T   (per batch: M=1024, N=768)
    tgemm_nt<<<dim3(DIM / 128, NQ / 128, BATCH), 256, SMEM_BYTES>>>(
        s, vpt, nullptr, out, LSEQ, DIM,
        (long)NQ * LSEQ, (long)DIM * LSEQ, (long)NQ * DIM, 0, 0);
}

// round 6
// speedup vs baseline: 1.3732x; 1.0157x over previous
#include <cuda_runtime.h>
#include <cstdint>
#include <cstddef>

#define BATCH 32
#define NQ    1024
#define LSEQ  512
#define DIM   768

// Scratch (device globals)
__device__ float g_rq [(size_t)BATCH * NQ   * DIM ];  // tf32-rounded q
__device__ float g_rk [(size_t)BATCH * LSEQ * DIM ];  // tf32-rounded k
__device__ float g_rv [(size_t)BATCH * LSEQ * DIM ];  // tf32-rounded v
__device__ float g_rw [3 * DIM * DIM];                // tf32-rounded q_w,k_w,v_w
__device__ float g_qp [(size_t)BATCH * NQ   * DIM ];
__device__ float g_kp [(size_t)BATCH * LSEQ * DIM ];
__device__ float g_vpt[(size_t)BATCH * DIM  * LSEQ];
__device__ float g_s  [(size_t)BATCH * NQ   * LSEQ];

__device__ __forceinline__ float tf32r(float x) {
    unsigned r; asm("cvt.rna.tf32.f32 %0,%1;" : "=r"(r) : "f"(x));
    return __uint_as_float(r);
}

__device__ __forceinline__ void mma_tf32(float c[4],
    unsigned a0, unsigned a1, unsigned a2, unsigned a3,
    unsigned b0, unsigned b1)
{
    asm("mma.sync.aligned.m16n8k8.row.col.f32.tf32.tf32.f32 "
        "{%0,%1,%2,%3},{%4,%5,%6,%7},{%8,%9},{%0,%1,%2,%3};"
        : "+f"(c[0]), "+f"(c[1]), "+f"(c[2]), "+f"(c[3])
        : "r"(a0), "r"(a1), "r"(a2), "r"(a3), "r"(b0), "r"(b1));
}

__device__ __forceinline__ void ldsm_x4(unsigned r[4], uint32_t addr) {
    asm volatile("ldmatrix.sync.aligned.m8n8.x4.shared.b16 {%0,%1,%2,%3}, [%4];"
        : "=r"(r[0]), "=r"(r[1]), "=r"(r[2]), "=r"(r[3]) : "r"(addr));
}

__device__ __forceinline__ void cp16(uint32_t dst, const void* src) {
    asm volatile("cp.async.cg.shared.global [%0], [%1], 16;" :: "r"(dst), "l"(src));
}
#define CP_COMMIT() asm volatile("cp.async.commit_group;" ::: "memory")
#define CP_WAIT1()  asm volatile("cp.async.wait_group 1;" ::: "memory")
#define CP_WAIT0()  asm volatile("cp.async.wait_group 0;" ::: "memory")

__device__ __forceinline__ uint32_t s2u(const void* p) {
    uint32_t a;
    asm("{ .reg .u64 t; cvta.to.shared.u64 t, %1; cvt.u32.u64 %0, t; }"
        : "=r"(a) : "l"(p));
    return a;
}

// ---------------------------------------------------------------------------
// 3-segment tf32 rounding: segments (s0->d0, len a4), (s1->d1, len b4),
// (s2->d2, rest). One launch replaces three.
// ---------------------------------------------------------------------------
__global__ __launch_bounds__(256) void round3_tf32(
    const float* __restrict__ s0, float* __restrict__ d0,
    const float* __restrict__ s1, float* __restrict__ d1,
    const float* __restrict__ s2, float* __restrict__ d2,
    int a4, int b4)
{
    int i = blockIdx.x * 256 + threadIdx.x;
    const float* src; float* dst; int j;
    if (i < a4)            { src = s0; dst = d0; j = i; }
    else if (i < a4 + b4)  { src = s1; dst = d1; j = i - a4; }
    else                   { src = s2; dst = d2; j = i - a4 - b4; }
    float4 v = ((const float4*)src)[j];
    v.x = tf32r(v.x); v.y = tf32r(v.y); v.z = tf32r(v.z); v.w = tf32r(v.w);
    ((float4*)dst)[j] = v;
}

// ---------------------------------------------------------------------------
// C[M,N] = A[M,K] @ B[N,K]^T (+bias). A,B row-major K-contiguous, tf32-exact.
// Block 128x128x32, 256 thr, warp grid 2x4, warp tile 64x32.
// Smem: [row][8 x 16B chunks], chunk XOR-swizzled by (row&7).
// cp.async 3-stage ring, 1 syncthreads/iter; ldmatrix x4 fragments.
// biasMode: 0 none, 1 col bias[n], 2 row bias[m]. roundOut: tf32-round stores.
// ---------------------------------------------------------------------------
#define TILE_B  16384
#define STAGE   (2 * TILE_B)
#define SMEM_BYTES (3 * STAGE)   // 98304

__global__ __launch_bounds__(256, 2) void tgemm_nt(
    const float* __restrict__ A, const float* __restrict__ Bm,
    const float* __restrict__ bias, float* __restrict__ C,
    int K, int Ntot, long sA, long sB, long sC, int biasMode, int roundOut)
{
    extern __shared__ char smem[];
    const uint32_t sb = s2u(smem);

    const int tid  = threadIdx.x;
    const int lane = tid & 31;
    const int wid  = tid >> 5;
    const int wm   = (wid >> 2) * 64;   // warp m offset (0,64)
    const int wn   = (wid & 3) * 32;    // warp n offset (0,32,64,96)
    const int gid  = lane >> 2;
    const int tig  = lane & 3;

    const float* Ab = A  + (size_t)blockIdx.z * sA + (size_t)blockIdx.y * 128 * K;
    const float* Bb = Bm + (size_t)blockIdx.z * sB + (size_t)blockIdx.x * 128 * K;
    float*       Cb = C  + (size_t)blockIdx.z * sC;

    const int crow  = tid >> 1;
    const int cbase = (tid & 1) * 4;
    const int nkt   = K / 32;

    auto issue = [&](int t) {
        const int s = t % 3;
        const uint32_t As = sb + s * STAGE;
        const uint32_t Bs = As + TILE_B;
        const float* ga = Ab + (size_t)crow * K + t * 32 + cbase * 4;
        const float* gb = Bb + (size_t)crow * K + t * 32 + cbase * 4;
        const uint32_t arow = As + (uint32_t)crow * 128;
        const uint32_t brow = Bs + (uint32_t)crow * 128;
        const int r7 = crow & 7;
        #pragma unroll
        for (int i = 0; i < 4; i++) {
            const uint32_t off = (uint32_t)(((cbase + i) ^ r7) * 16);
            cp16(arow + off, ga + i * 4);
            cp16(brow + off, gb + i * 4);
        }
        CP_COMMIT();
    };

    issue(0); issue(1);

    float acc[4][4][4];
    #pragma unroll
    for (int mi = 0; mi < 4; mi++)
        #pragma unroll
        for (int nj = 0; nj < 4; nj++)
            #pragma unroll
            for (int r = 0; r < 4; r++) acc[mi][nj][r] = 0.f;

    // A x4: lanes 0-15 -> rows (chunk +0), lanes 16-31 -> rows (chunk +1)
    const int la15 = lane & 15;
    const int lahi = lane >> 4;
    // B x4 (two 8-col fragments + both k-halves in one load):
    //   lanes 0-7:   rows p*16+0..7,  chunk +0   -> reg0 = b[2p][0]
    //   lanes 8-15:  rows p*16+0..7,  chunk +1   -> reg1 = b[2p][1]
    //   lanes 16-23: rows p*16+8..15, chunk +0   -> reg2 = b[2p+1][0]
    //   lanes 24-31: rows p*16+8..15, chunk +1   -> reg3 = b[2p+1][1]
    const int lbrow = ((lane >> 4) * 8) + (lane & 7);
    const int lbhi  = (lane >> 3) & 1;

    for (int t = 0; t < nkt; t++) {
        const uint32_t As = sb + (t % 3) * STAGE;
        const uint32_t Bs = As + TILE_B;

        CP_WAIT1();
        __syncthreads();
        if (t + 2 < nkt) issue(t + 2);

        #pragma unroll
        for (int kk = 0; kk < 4; kk++) {
            unsigned a[4][4], bq[2][4];
            #pragma unroll
            for (int mi = 0; mi < 4; mi++) {
                const int rowA = wm + mi * 16 + la15;
                const uint32_t addr = As + (uint32_t)rowA * 128
                    + (uint32_t)((((kk * 2) + lahi) ^ (rowA & 7)) * 16);
                ldsm_x4(a[mi], addr);
            }
            #pragma unroll
            for (int p = 0; p < 2; p++) {
                const int rowB = wn + p * 16 + lbrow;
                const uint32_t addr = Bs + (uint32_t)rowB * 128
                    + (uint32_t)((((kk * 2) + lbhi) ^ (rowB & 7)) * 16);
                ldsm_x4(bq[p], addr);
            }
            #pragma unroll
            for (int mi = 0; mi < 4; mi++)
                #pragma unroll
                for (int nj = 0; nj < 4; nj++)
                    mma_tf32(acc[mi][nj], a[mi][0], a[mi][1], a[mi][2], a[mi][3],
                             bq[nj >> 1][(nj & 1) * 2], bq[nj >> 1][(nj & 1) * 2 + 1]);
        }
    }
    CP_WAIT0();

    // ---- epilogue ----
    #pragma unroll
    for (int mi = 0; mi < 4; mi++) {
        const int row0 = blockIdx.y * 128 + wm + mi * 16 + gid;
        float rb0 = (biasMode == 2) ? __ldg(bias + row0)     : 0.f;
        float rb1 = (biasMode == 2) ? __ldg(bias + row0 + 8) : 0.f;
        #pragma unroll
        for (int nj = 0; nj < 4; nj++) {
            const int col = blockIdx.x * 128 + wn + nj * 8 + 2 * tig;
            float c0 = acc[mi][nj][0], c1 = acc[mi][nj][1];
            float c2 = acc[mi][nj][2], c3 = acc[mi][nj][3];
            if (biasMode == 1) {
                float b0 = __ldg(bias + col), b1 = __ldg(bias + col + 1);
                c0 += b0; c1 += b1; c2 += b0; c3 += b1;
            } else if (biasMode == 2) {
                c0 += rb0; c1 += rb0; c2 += rb1; c3 += rb1;
            }
            if (roundOut) {
                c0 = tf32r(c0); c1 = tf32r(c1); c2 = tf32r(c2); c3 = tf32r(c3);
            }
            *(float2*)(Cb + (size_t)row0 * Ntot + col)       = make_float2(c0, c1);
            *(float2*)(Cb + (size_t)(row0 + 8) * Ntot + col) = make_float2(c2, c3);
        }
    }
}

// ---------------------------------------------------------------------------
// In-place scaled softmax over rows of 512; outputs tf32-rounded.
// ---------------------------------------------------------------------------
__global__ __launch_bounds__(256) void softmax_rows(float* __restrict__ S, float scale)
{
    const int row  = blockIdx.x * 8 + (threadIdx.x >> 5);
    const int lane = threadIdx.x & 31;
    float4* r4 = (float4*)(S + (size_t)row * LSEQ) + lane;

    float4 v[4];
    #pragma unroll
    for (int i = 0; i < 4; i++) {
        v[i] = r4[32 * i];
        v[i].x *= scale; v[i].y *= scale; v[i].z *= scale; v[i].w *= scale;
    }
    float mx = -3.4e38f;
    #pragma unroll
    for (int i = 0; i < 4; i++)
        mx = fmaxf(mx, fmaxf(fmaxf(v[i].x, v[i].y), fmaxf(v[i].z, v[i].w)));
    #pragma unroll
    for (int o = 16; o > 0; o >>= 1)
        mx = fmaxf(mx, __shfl_xor_sync(0xffffffffu, mx, o));
    float sum = 0.f;
    #pragma unroll
    for (int i = 0; i < 4; i++) {
        v[i].x = __expf(v[i].x - mx); v[i].y = __expf(v[i].y - mx);
        v[i].z = __expf(v[i].z - mx); v[i].w = __expf(v[i].w - mx);
        sum += v[i].x + v[i].y + v[i].z + v[i].w;
    }
    #pragma unroll
    for (int o = 16; o > 0; o >>= 1)
        sum += __shfl_xor_sync(0xffffffffu, sum, o);
    const float inv = 1.0f / sum;
    #pragma unroll
    for (int i = 0; i < 4; i++) {
        v[i].x = tf32r(v[i].x * inv); v[i].y = tf32r(v[i].y * inv);
        v[i].z = tf32r(v[i].z * inv); v[i].w = tf32r(v[i].w * inv);
        r4[32 * i] = v[i];
    }
}

extern "C" void kernel_launch(void* const* d_in, const int* in_sizes, int n_in,
                              void* d_out, int out_size)
{
    const float* q   = (const float*)d_in[0];
    const float* k   = (const float*)d_in[1];
    const float* v   = (const float*)d_in[2];
    const float* q_w = (const float*)d_in[3];
    const float* q_b = (const float*)d_in[4];
    const float* k_w = (const float*)d_in[5];
    const float* k_b = (const float*)d_in[6];
    const float* v_w = (const float*)d_in[7];
    const float* v_b = (const float*)d_in[8];
    float* out = (float*)d_out;

    float *rq, *rk, *rv, *rw, *qp, *kp, *vpt, *s;
    cudaGetSymbolAddress((void**)&rq,  g_rq);
    cudaGetSymbolAddress((void**)&rk,  g_rk);
    cudaGetSymbolAddress((void**)&rv,  g_rv);
    cudaGetSymbolAddress((void**)&rw,  g_rw);
    cudaGetSymbolAddress((void**)&qp,  g_qp);
    cudaGetSymbolAddress((void**)&kp,  g_kp);
    cudaGetSymbolAddress((void**)&vpt, g_vpt);
    cudaGetSymbolAddress((void**)&s,   g_s);

    cudaFuncSetAttribute(tgemm_nt, cudaFuncAttributeMaxDynamicSharedMemorySize, SMEM_BYTES);

    const int nq4 = BATCH * NQ * DIM / 4;
    const int nk4 = BATCH * LSEQ * DIM / 4;
    const int nw4 = DIM * DIM / 4;

    // launch 0: round q -> rq, k -> rk, v -> rv
    round3_tf32<<<(nq4 + 2 * nk4) / 256, 256>>>(q, rq, k, rk, v, rv, nq4, nk4);
    // launch 1: round q_w,k_w,v_w -> rw (contiguous thirds)
    round3_tf32<<<3 * nw4 / 256, 256>>>(q_w, rw, k_w, rw + (size_t)DIM * DIM,
                                        v_w, rw + 2 * (size_t)DIM * DIM, nw4, nw4);

    // launch 2: qp = rq @ qw^T + qb   (M=32768, N=768)
    tgemm_nt<<<dim3(DIM / 128, (BATCH * NQ) / 128, 1), 256, SMEM_BYTES>>>(
        rq, rw, q_b, qp, DIM, DIM, 0, 0, 0, 1, 1);
    // launch 3: kp = rk @ kw^T + kb   (M=16384, N=768)
    tgemm_nt<<<dim3(DIM / 128, (BATCH * LSEQ) / 128, 1), 256, SMEM_BYTES>>>(
        rk, rw + (size_t)DIM * DIM, k_b, kp, DIM, DIM, 0, 0, 0, 1, 1);
    // launch 4: vpT[b,d,l] = vw @ rv[b]^T + vb[d]  (M=768, N=512, row bias)
    tgemm_nt<<<dim3(LSEQ / 128, DIM / 128, BATCH), 256, SMEM_BYTES>>>(
        rw + 2 * (size_t)DIM * DIM, rv, v_b, vpt, DIM, LSEQ,
        0, (long)LSEQ * DIM, (long)DIM * LSEQ, 2, 1);
    // launch 5 (ncu target): S[b] = qp[b] @ kp[b]^T   (M=1024, N=512)
    tgemm_nt<<<dim3(LSEQ / 128, NQ / 128, BATCH), 256, SMEM_BYTES>>>(
        qp, kp, nullptr, s, DIM, LSEQ,
        (long)NQ * DIM, (long)LSEQ * DIM, (long)NQ * LSEQ, 0, 0);
    // softmax (rounds output to tf32)
    softmax_rows<<<(BATCH * NQ) / 8, 256>>>(s, 0.03608439182435161f);
    // out[b] = P[b] @ vpT[b]^T   (M=1024, N=768)
    tgemm_nt<<<dim3(DIM / 128, NQ / 128, BATCH), 256, SMEM_BYTES>>>(
        s, vpt, nullptr, out, LSEQ, DIM,
        (long)NQ * LSEQ, (long)DIM * LSEQ, (long)NQ * DIM, 0, 0);
}

// round 7
// speedup vs baseline: 1.4869x; 1.0828x over previous
#include <cuda_runtime.h>
#include <cstdint>
#include <cstddef>

#define BATCH 32
#define NQ    1024
#define LSEQ  512
#define DIM   768

// Scratch (device globals)
__device__ float g_rq  [(size_t)BATCH * NQ   * DIM ];  // tf32-rounded q
__device__ float g_rk  [(size_t)BATCH * LSEQ * DIM ];  // tf32-rounded k
__device__ float g_rv  [(size_t)BATCH * LSEQ * DIM ];  // tf32-rounded v
__device__ float g_rwv [DIM * DIM];                    // tf32-rounded v_w
__device__ float g_rwqt[DIM * DIM];                    // tf32-rounded q_w^T  [c][d]
__device__ float g_rwkt[DIM * DIM];                    // tf32-rounded k_w^T  [c][d]
__device__ float g_gt  [DIM * DIM];                    // Gt[c'][c] = sum_d kw[d,c']qw[d,c]
__device__ float g_w2  [DIM];                          // w2[c] = sum_d bq[d] kw[d,c]
__device__ float g_s2  [(size_t)BATCH * LSEQ];         // s2[b,l] = k[b,l,:].w2
__device__ float g_qg  [(size_t)BATCH * NQ   * DIM ];  // qG [b][n][c']
__device__ float g_vpt [(size_t)BATCH * DIM  * LSEQ];  // vpT [b][d][l]
__device__ float g_s   [(size_t)BATCH * NQ   * LSEQ];  // S/P [b][n][l]

__device__ __forceinline__ float tf32r(float x) {
    unsigned r; asm("cvt.rna.tf32.f32 %0,%1;" : "=r"(r) : "f"(x));
    return __uint_as_float(r);
}

__device__ __forceinline__ void mma_tf32(float c[4],
    unsigned a0, unsigned a1, unsigned a2, unsigned a3,
    unsigned b0, unsigned b1)
{
    asm("mma.sync.aligned.m16n8k8.row.col.f32.tf32.tf32.f32 "
        "{%0,%1,%2,%3},{%4,%5,%6,%7},{%8,%9},{%0,%1,%2,%3};"
        : "+f"(c[0]), "+f"(c[1]), "+f"(c[2]), "+f"(c[3])
        : "r"(a0), "r"(a1), "r"(a2), "r"(a3), "r"(b0), "r"(b1));
}

__device__ __forceinline__ void ldsm_x4(unsigned r[4], uint32_t addr) {
    asm volatile("ldmatrix.sync.aligned.m8n8.x4.shared.b16 {%0,%1,%2,%3}, [%4];"
        : "=r"(r[0]), "=r"(r[1]), "=r"(r[2]), "=r"(r[3]) : "r"(addr));
}

__device__ __forceinline__ void cp16(uint32_t dst, const void* src) {
    asm volatile("cp.async.cg.shared.global [%0], [%1], 16;" :: "r"(dst), "l"(src));
}
#define CP_COMMIT() asm volatile("cp.async.commit_group;" ::: "memory")
#define CP_WAIT1()  asm volatile("cp.async.wait_group 1;" ::: "memory")
#define CP_WAIT0()  asm volatile("cp.async.wait_group 0;" ::: "memory")

__device__ __forceinline__ uint32_t s2u(const void* p) {
    uint32_t a;
    asm("{ .reg .u64 t; cvta.to.shared.u64 t, %1; cvt.u32.u64 %0, t; }"
        : "=r"(a) : "l"(p));
    return a;
}

// ---------------------------------------------------------------------------
// 3-segment tf32 rounding
// ---------------------------------------------------------------------------
__global__ __launch_bounds__(256) void round3_tf32(
    const float* __restrict__ s0, float* __restrict__ d0,
    const float* __restrict__ s1, float* __restrict__ d1,
    const float* __restrict__ s2, float* __restrict__ d2,
    int a4, int b4)
{
    int i = blockIdx.x * 256 + threadIdx.x;
    const float* src; float* dst; int j;
    if (i < a4)            { src = s0; dst = d0; j = i; }
    else if (i < a4 + b4)  { src = s1; dst = d1; j = i - a4; }
    else                   { src = s2; dst = d2; j = i - a4 - b4; }
    float4 v = ((const float4*)src)[j];
    v.x = tf32r(v.x); v.y = tf32r(v.y); v.z = tf32r(v.z); v.w = tf32r(v.w);
    ((float4*)dst)[j] = v;
}

// ---------------------------------------------------------------------------
// 768x768 transpose + tf32 round. z=0: q_w -> rwqt, z=1: k_w -> rwkt.
// dst[c][d] = round(src[d][c])
// ---------------------------------------------------------------------------
__global__ __launch_bounds__(256) void transpose_round(
    const float* __restrict__ qw, float* __restrict__ dqt,
    const float* __restrict__ kw, float* __restrict__ dkt)
{
    __shared__ float tile[32][33];
    const float* src = blockIdx.z ? kw : qw;
    float*       dst = blockIdx.z ? dkt : dqt;
    const int tx = threadIdx.x, ty = threadIdx.y;
    const int x = blockIdx.x * 32 + tx;
    const int y = blockIdx.y * 32 + ty;
    #pragma unroll
    for (int i = 0; i < 32; i += 8)
        tile[ty + i][tx] = src[(size_t)(y + i) * DIM + x];
    __syncthreads();
    const int xo = blockIdx.y * 32 + tx;
    const int yo = blockIdx.x * 32 + ty;
    #pragma unroll
    for (int i = 0; i < 32; i += 8)
        dst[(size_t)(yo + i) * DIM + xo] = tf32r(tile[tx][ty + i]);
}

// ---------------------------------------------------------------------------
// w2[c] = sum_d bq[d] * k_w[d*768 + c]
// ---------------------------------------------------------------------------
__global__ __launch_bounds__(256) void compute_w2(
    const float* __restrict__ kw, const float* __restrict__ bq,
    float* __restrict__ w2)
{
    const int c = blockIdx.x * 256 + threadIdx.x;
    float acc = 0.f;
    for (int d = 0; d < DIM; d++)
        acc += __ldg(bq + d) * __ldg(kw + (size_t)d * DIM + c);
    w2[c] = acc;
}

// ---------------------------------------------------------------------------
// s2[row] = rk[row,:] . w2   (row = b*LSEQ + l), one warp per row
// ---------------------------------------------------------------------------
__global__ __launch_bounds__(256) void compute_s2(
    const float* __restrict__ rk, const float* __restrict__ w2,
    float* __restrict__ s2)
{
    const int row  = blockIdx.x * 8 + (threadIdx.x >> 5);
    const int lane = threadIdx.x & 31;
    const float4* kr = (const float4*)(rk + (size_t)row * DIM);
    const float4* w4 = (const float4*)w2;
    float acc = 0.f;
    #pragma unroll
    for (int i = 0; i < 6; i++) {
        float4 a = kr[lane + 32 * i];
        float4 b = __ldg(w4 + lane + 32 * i);
        acc += a.x * b.x + a.y * b.y + a.z * b.z + a.w * b.w;
    }
    #pragma unroll
    for (int o = 16; o > 0; o >>= 1)
        acc += __shfl_xor_sync(0xffffffffu, acc, o);
    if (lane == 0) s2[row] = acc;
}

// ---------------------------------------------------------------------------
// C[M,N] = A[M,K] @ B[N,K]^T (+bias). A,B row-major K-contiguous, tf32-exact.
// Block 128x128x32, 256 thr, warp grid 2x4, warp tile 64x32.
// cp.async 3-stage ring, ldmatrix x4 fragments, XOR swizzle.
// biasMode: 0 none, 1 col bias[n], 2 row bias[m]. roundOut: tf32-round stores.
// ---------------------------------------------------------------------------
#define TILE_B  16384
#define STAGE   (2 * TILE_B)
#define SMEM_BYTES (3 * STAGE)   // 98304

__global__ __launch_bounds__(256, 2) void tgemm_nt(
    const float* __restrict__ A, const float* __restrict__ Bm,
    const float* __restrict__ bias, float* __restrict__ C,
    int K, int Ntot, long sA, long sB, long sC, int biasMode, int roundOut)
{
    extern __shared__ char smem[];
    const uint32_t sb = s2u(smem);

    const int tid  = threadIdx.x;
    const int lane = tid & 31;
    const int wid  = tid >> 5;
    const int wm   = (wid >> 2) * 64;
    const int wn   = (wid & 3) * 32;
    const int gid  = lane >> 2;
    const int tig  = lane & 3;

    const float* Ab = A  + (size_t)blockIdx.z * sA + (size_t)blockIdx.y * 128 * K;
    const float* Bb = Bm + (size_t)blockIdx.z * sB + (size_t)blockIdx.x * 128 * K;
    float*       Cb = C  + (size_t)blockIdx.z * sC;

    const int crow  = tid >> 1;
    const int cbase = (tid & 1) * 4;
    const int nkt   = K / 32;

    auto issue = [&](int t) {
        const int s = t % 3;
        const uint32_t As = sb + s * STAGE;
        const uint32_t Bs = As + TILE_B;
        const float* ga = Ab + (size_t)crow * K + t * 32 + cbase * 4;
        const float* gb = Bb + (size_t)crow * K + t * 32 + cbase * 4;
        const uint32_t arow = As + (uint32_t)crow * 128;
        const uint32_t brow = Bs + (uint32_t)crow * 128;
        const int r7 = crow & 7;
        #pragma unroll
        for (int i = 0; i < 4; i++) {
            const uint32_t off = (uint32_t)(((cbase + i) ^ r7) * 16);
            cp16(arow + off, ga + i * 4);
            cp16(brow + off, gb + i * 4);
        }
        CP_COMMIT();
    };

    issue(0); issue(1);

    float acc[4][4][4];
    #pragma unroll
    for (int mi = 0; mi < 4; mi++)
        #pragma unroll
        for (int nj = 0; nj < 4; nj++)
            #pragma unroll
            for (int r = 0; r < 4; r++) acc[mi][nj][r] = 0.f;

    const int la15 = lane & 15;
    const int lahi = lane >> 4;
    const int lbrow = ((lane >> 4) * 8) + (lane & 7);
    const int lbhi  = (lane >> 3) & 1;

    for (int t = 0; t < nkt; t++) {
        const uint32_t As = sb + (t % 3) * STAGE;
        const uint32_t Bs = As + TILE_B;

        CP_WAIT1();
        __syncthreads();
        if (t + 2 < nkt) issue(t + 2);

        #pragma unroll
        for (int kk = 0; kk < 4; kk++) {
            unsigned a[4][4], bq[2][4];
            #pragma unroll
            for (int mi = 0; mi < 4; mi++) {
                const int rowA = wm + mi * 16 + la15;
                const uint32_t addr = As + (uint32_t)rowA * 128
                    + (uint32_t)((((kk * 2) + lahi) ^ (rowA & 7)) * 16);
                ldsm_x4(a[mi], addr);
            }
            #pragma unroll
            for (int p = 0; p < 2; p++) {
                const int rowB = wn + p * 16 + lbrow;
                const uint32_t addr = Bs + (uint32_t)rowB * 128
                    + (uint32_t)((((kk * 2) + lbhi) ^ (rowB & 7)) * 16);
                ldsm_x4(bq[p], addr);
            }
            #pragma unroll
            for (int mi = 0; mi < 4; mi++)
                #pragma unroll
                for (int nj = 0; nj < 4; nj++)
                    mma_tf32(acc[mi][nj], a[mi][0], a[mi][1], a[mi][2], a[mi][3],
                             bq[nj >> 1][(nj & 1) * 2], bq[nj >> 1][(nj & 1) * 2 + 1]);
        }
    }
    CP_WAIT0();

    // ---- epilogue ----
    #pragma unroll
    for (int mi = 0; mi < 4; mi++) {
        const int row0 = blockIdx.y * 128 + wm + mi * 16 + gid;
        float rb0 = (biasMode == 2) ? __ldg(bias + row0)     : 0.f;
        float rb1 = (biasMode == 2) ? __ldg(bias + row0 + 8) : 0.f;
        #pragma unroll
        for (int nj = 0; nj < 4; nj++) {
            const int col = blockIdx.x * 128 + wn + nj * 8 + 2 * tig;
            float c0 = acc[mi][nj][0], c1 = acc[mi][nj][1];
            float c2 = acc[mi][nj][2], c3 = acc[mi][nj][3];
            if (biasMode == 1) {
                float b0 = __ldg(bias + col), b1 = __ldg(bias + col + 1);
                c0 += b0; c1 += b1; c2 += b0; c3 += b1;
            } else if (biasMode == 2) {
                c0 += rb0; c1 += rb0; c2 += rb1; c3 += rb1;
            }
            if (roundOut) {
                c0 = tf32r(c0); c1 = tf32r(c1); c2 = tf32r(c2); c3 = tf32r(c3);
            }
            *(float2*)(Cb + (size_t)row0 * Ntot + col)       = make_float2(c0, c1);
            *(float2*)(Cb + (size_t)(row0 + 8) * Ntot + col) = make_float2(c2, c3);
        }
    }
}

// ---------------------------------------------------------------------------
// In-place scaled softmax over rows of 512 with additive col bias s2[b,l];
// outputs tf32-rounded.
// ---------------------------------------------------------------------------
__global__ __launch_bounds__(256) void softmax_rows(
    float* __restrict__ S, const float* __restrict__ s2, float scale)
{
    const int row  = blockIdx.x * 8 + (threadIdx.x >> 5);
    const int lane = threadIdx.x & 31;
    const int b    = row >> 10;              // row = b*NQ + n
    float4* r4 = (float4*)(S + (size_t)row * LSEQ) + lane;
    const float4* b4 = (const float4*)(s2 + (size_t)b * LSEQ) + lane;

    float4 v[4];
    #pragma unroll
    for (int i = 0; i < 4; i++) {
        v[i] = r4[32 * i];
        float4 w = __ldg(b4 + 32 * i);
        v[i].x = (v[i].x + w.x) * scale; v[i].y = (v[i].y + w.y) * scale;
        v[i].z = (v[i].z + w.z) * scale; v[i].w = (v[i].w + w.w) * scale;
    }
    float mx = -3.4e38f;
    #pragma unroll
    for (int i = 0; i < 4; i++)
        mx = fmaxf(mx, fmaxf(fmaxf(v[i].x, v[i].y), fmaxf(v[i].z, v[i].w)));
    #pragma unroll
    for (int o = 16; o > 0; o >>= 1)
        mx = fmaxf(mx, __shfl_xor_sync(0xffffffffu, mx, o));
    float sum = 0.f;
    #pragma unroll
    for (int i = 0; i < 4; i++) {
        v[i].x = __expf(v[i].x - mx); v[i].y = __expf(v[i].y - mx);
        v[i].z = __expf(v[i].z - mx); v[i].w = __expf(v[i].w - mx);
        sum += v[i].x + v[i].y + v[i].z + v[i].w;
    }
    #pragma unroll
    for (int o = 16; o > 0; o >>= 1)
        sum += __shfl_xor_sync(0xffffffffu, sum, o);
    const float inv = 1.0f / sum;
    #pragma unroll
    for (int i = 0; i < 4; i++) {
        v[i].x = tf32r(v[i].x * inv); v[i].y = tf32r(v[i].y * inv);
        v[i].z = tf32r(v[i].z * inv); v[i].w = tf32r(v[i].w * inv);
        r4[32 * i] = v[i];
    }
}

extern "C" void kernel_launch(void* const* d_in, const int* in_sizes, int n_in,
                              void* d_out, int out_size)
{
    const float* q   = (const float*)d_in[0];
    const float* k   = (const float*)d_in[1];
    const float* v   = (const float*)d_in[2];
    const float* q_w = (const float*)d_in[3];
    const float* q_b = (const float*)d_in[4];
    const float* k_w = (const float*)d_in[5];
    const float* v_w = (const float*)d_in[7];
    const float* v_b = (const float*)d_in[8];
    float* out = (float*)d_out;

    float *rq, *rk, *rv, *rwv, *rwqt, *rwkt, *gt, *w2, *s2, *qg, *vpt, *s;
    cudaGetSymbolAddress((void**)&rq,   g_rq);
    cudaGetSymbolAddress((void**)&rk,   g_rk);
    cudaGetSymbolAddress((void**)&rv,   g_rv);
    cudaGetSymbolAddress((void**)&rwv,  g_rwv);
    cudaGetSymbolAddress((void**)&rwqt, g_rwqt);
    cudaGetSymbolAddress((void**)&rwkt, g_rwkt);
    cudaGetSymbolAddress((void**)&gt,   g_gt);
    cudaGetSymbolAddress((void**)&w2,   g_w2);
    cudaGetSymbolAddress((void**)&s2,   g_s2);
    cudaGetSymbolAddress((void**)&qg,   g_qg);
    cudaGetSymbolAddress((void**)&vpt,  g_vpt);
    cudaGetSymbolAddress((void**)&s,    g_s);

    cudaFuncSetAttribute(tgemm_nt, cudaFuncAttributeMaxDynamicSharedMemorySize, SMEM_BYTES);

    const int nq4 = BATCH * NQ * DIM / 4;
    const int nk4 = BATCH * LSEQ * DIM / 4;
    const int nw4 = DIM * DIM / 4;

    // 0: round q,k,v
    round3_tf32<<<(nq4 + 2 * nk4) / 256, 256>>>(q, rq, k, rk, v, rv, nq4, nk4);
    // 1: round v_w
    round3_tf32<<<nw4 / 256, 256>>>(v_w, rwv, v_w, rwv, v_w, rwv, nw4, 0);
    // 2: transpose+round q_w -> rwqt, k_w -> rwkt
    transpose_round<<<dim3(24, 24, 2), dim3(32, 8)>>>(q_w, rwqt, k_w, rwkt);
    // 3: w2[c] = sum_d bq[d] k_w[d,c]
    compute_w2<<<DIM / 256, 256>>>(k_w, q_b, w2);
    // 4: Gt[c'][c] = sum_d kw[d,c'] qw[d,c]  (NT: A=rwkt, B=rwqt)
    tgemm_nt<<<dim3(DIM / 128, DIM / 128, 1), 256, SMEM_BYTES>>>(
        rwkt, rwqt, nullptr, gt, DIM, DIM, 0, 0, 0, 0, 1);
    // 5 (ncu target): qG[n,c'] = sum_c rq[n,c] Gt[c',c]  (M=32768, N=768)
    tgemm_nt<<<dim3(DIM / 128, (BATCH * NQ) / 128, 1), 256, SMEM_BYTES>>>(
        rq, gt, nullptr, qg, DIM, DIM, 0, 0, 0, 0, 1);
    // 6: vpT[b,d,l] = vw @ rv[b]^T + vb[d]  (M=768, N=512, row bias)
    tgemm_nt<<<dim3(LSEQ / 128, DIM / 128, BATCH), 256, SMEM_BYTES>>>(
        rwv, rv, v_b, vpt, DIM, LSEQ,
        0, (long)LSEQ * DIM, (long)DIM * LSEQ, 2, 1);
    // 7: S[b] = qG[b] @ rk[b]^T   (M=1024, N=512, K=768)
    tgemm_nt<<<dim3(LSEQ / 128, NQ / 128, BATCH), 256, SMEM_BYTES>>>(
        qg, rk, nullptr, s, DIM, LSEQ,
        (long)NQ * DIM, (long)LSEQ * DIM, (long)NQ * LSEQ, 0, 0);
    // 8: s2[b,l] = rk[b,l,:] . w2
    compute_s2<<<(BATCH * LSEQ) / 8, 256>>>(rk, w2, s2);
    // 9: softmax((S + s2) * scale), tf32-rounded output
    softmax_rows<<<(BATCH * NQ) / 8, 256>>>(s, s2, 0.03608439182435161f);
    // 10: out[b] = P[b] @ vpT[b]^T   (M=1024, N=768, K=512)
    tgemm_nt<<<dim3(DIM / 128, NQ / 128, BATCH), 256, SMEM_BYTES>>>(
        s, vpt, nullptr, out, LSEQ, DIM,
        (long)NQ * LSEQ, (long)DIM * LSEQ, (long)NQ * DIM, 0, 0);
}

// round 8
// speedup vs baseline: 1.5290x; 1.0283x over previous
#include <cuda_runtime.h>
#include <cstdint>
#include <cstddef>

#define BATCH 32
#define NQ    1024
#define LSEQ  512
#define DIM   768

// Scratch (device globals)
__device__ float g_rq  [(size_t)BATCH * NQ   * DIM ];  // tf32-rounded q
__device__ float g_rk  [(size_t)BATCH * LSEQ * DIM ];  // tf32-rounded k
__device__ float g_rv  [(size_t)BATCH * LSEQ * DIM ];  // tf32-rounded v
__device__ float g_rwv [DIM * DIM];                    // tf32-rounded v_w
__device__ float g_rwqt[DIM * DIM];                    // tf32-rounded q_w^T  [c][d]
__device__ float g_rwkt[DIM * DIM];                    // tf32-rounded k_w^T  [c][d]
__device__ float g_gt  [DIM * DIM];                    // Gt[c'][c] = sum_d kw[d,c']qw[d,c]
__device__ float g_w2  [DIM];                          // w2[c] = sum_d bq[d] kw[d,c]
__device__ float g_s2  [(size_t)BATCH * LSEQ];         // s2[b,l] = k[b,l,:].w2
__device__ float g_qg  [(size_t)BATCH * NQ   * DIM ];  // qG [b][n][c']
__device__ float g_vpt [(size_t)BATCH * DIM  * LSEQ];  // vpT [b][d][l]
__device__ float g_s   [(size_t)BATCH * NQ   * LSEQ];  // S/P [b][n][l]

__device__ __forceinline__ float tf32r(float x) {
    unsigned r; asm("cvt.rna.tf32.f32 %0,%1;" : "=r"(r) : "f"(x));
    return __uint_as_float(r);
}

__device__ __forceinline__ void mma_tf32(float c[4],
    unsigned a0, unsigned a1, unsigned a2, unsigned a3,
    unsigned b0, unsigned b1)
{
    asm("mma.sync.aligned.m16n8k8.row.col.f32.tf32.tf32.f32 "
        "{%0,%1,%2,%3},{%4,%5,%6,%7},{%8,%9},{%0,%1,%2,%3};"
        : "+f"(c[0]), "+f"(c[1]), "+f"(c[2]), "+f"(c[3])
        : "r"(a0), "r"(a1), "r"(a2), "r"(a3), "r"(b0), "r"(b1));
}

__device__ __forceinline__ void ldsm_x4(unsigned r[4], uint32_t addr) {
    asm volatile("ldmatrix.sync.aligned.m8n8.x4.shared.b16 {%0,%1,%2,%3}, [%4];"
        : "=r"(r[0]), "=r"(r[1]), "=r"(r[2]), "=r"(r[3]) : "r"(addr));
}

__device__ __forceinline__ void cp16(uint32_t dst, const void* src) {
    asm volatile("cp.async.cg.shared.global [%0], [%1], 16;" :: "r"(dst), "l"(src));
}
#define CP_COMMIT() asm volatile("cp.async.commit_group;" ::: "memory")
#define CP_WAIT1()  asm volatile("cp.async.wait_group 1;" ::: "memory")
#define CP_WAIT0()  asm volatile("cp.async.wait_group 0;" ::: "memory")

__device__ __forceinline__ uint32_t s2u(const void* p) {
    uint32_t a;
    asm("{ .reg .u64 t; cvta.to.shared.u64 t, %1; cvt.u32.u64 %0, t; }"
        : "=r"(a) : "l"(p));
    return a;
}

// ---------------------------------------------------------------------------
// 3-segment tf32 rounding
// ---------------------------------------------------------------------------
__global__ __launch_bounds__(256) void round3_tf32(
    const float* __restrict__ s0, float* __restrict__ d0,
    const float* __restrict__ s1, float* __restrict__ d1,
    const float* __restrict__ s2, float* __restrict__ d2,
    int a4, int b4)
{
    int i = blockIdx.x * 256 + threadIdx.x;
    const float* src; float* dst; int j;
    if (i < a4)            { src = s0; dst = d0; j = i; }
    else if (i < a4 + b4)  { src = s1; dst = d1; j = i - a4; }
    else                   { src = s2; dst = d2; j = i - a4 - b4; }
    float4 v = ((const float4*)src)[j];
    v.x = tf32r(v.x); v.y = tf32r(v.y); v.z = tf32r(v.z); v.w = tf32r(v.w);
    ((float4*)dst)[j] = v;
}

// ---------------------------------------------------------------------------
// z=0: q_w -> rwqt transposed+rounded; z=1: k_w -> rwkt transposed+rounded;
// z=2: v_w -> rwv rounded (no transpose).
// ---------------------------------------------------------------------------
__global__ __launch_bounds__(256) void transpose_round(
    const float* __restrict__ qw, float* __restrict__ dqt,
    const float* __restrict__ kw, float* __restrict__ dkt,
    const float* __restrict__ vw, float* __restrict__ dv)
{
    const int tx = threadIdx.x, ty = threadIdx.y;
    const int x = blockIdx.x * 32 + tx;
    const int y = blockIdx.y * 32 + ty;

    if (blockIdx.z == 2) {
        #pragma unroll
        for (int i = 0; i < 32; i += 8)
            dv[(size_t)(y + i) * DIM + x] = tf32r(vw[(size_t)(y + i) * DIM + x]);
        return;
    }

    __shared__ float tile[32][33];
    const float* src = blockIdx.z ? kw : qw;
    float*       dst = blockIdx.z ? dkt : dqt;
    #pragma unroll
    for (int i = 0; i < 32; i += 8)
        tile[ty + i][tx] = src[(size_t)(y + i) * DIM + x];
    __syncthreads();
    const int xo = blockIdx.y * 32 + tx;
    const int yo = blockIdx.x * 32 + ty;
    #pragma unroll
    for (int i = 0; i < 32; i += 8)
        dst[(size_t)(yo + i) * DIM + xo] = tf32r(tile[tx][ty + i]);
}

// ---------------------------------------------------------------------------
// w2[c] = sum_d bq[d] * k_w[d*768 + c]
// 24 blocks x 256 thr = (8 d-groups x 32 cols); coalesced rows, smem reduce.
// ---------------------------------------------------------------------------
__global__ __launch_bounds__(256) void compute_w2(
    const float* __restrict__ kw, const float* __restrict__ bq,
    float* __restrict__ w2)
{
    __shared__ float part[8][32];
    const int cl = threadIdx.x & 31;
    const int dg = threadIdx.x >> 5;
    const int c  = blockIdx.x * 32 + cl;
    float acc = 0.f;
    const int d0 = dg * 96;
    #pragma unroll 8
    for (int d = d0; d < d0 + 96; d++)
        acc += __ldg(bq + d) * __ldg(kw + (size_t)d * DIM + c);
    part[dg][cl] = acc;
    __syncthreads();
    if (dg == 0) {
        float s = 0.f;
        #pragma unroll
        for (int i = 0; i < 8; i++) s += part[i][cl];
        w2[c] = s;
    }
}

// ---------------------------------------------------------------------------
// s2[row] = rk[row,:] . w2   (row = b*LSEQ + l), one warp per row
// ---------------------------------------------------------------------------
__global__ __launch_bounds__(256) void compute_s2(
    const float* __restrict__ rk, const float* __restrict__ w2,
    float* __restrict__ s2)
{
    const int row  = blockIdx.x * 8 + (threadIdx.x >> 5);
    const int lane = threadIdx.x & 31;
    const float4* kr = (const float4*)(rk + (size_t)row * DIM);
    const float4* w4 = (const float4*)w2;
    float acc = 0.f;
    #pragma unroll
    for (int i = 0; i < 6; i++) {
        float4 a = kr[lane + 32 * i];
        float4 b = __ldg(w4 + lane + 32 * i);
        acc += a.x * b.x + a.y * b.y + a.z * b.z + a.w * b.w;
    }
    #pragma unroll
    for (int o = 16; o > 0; o >>= 1)
        acc += __shfl_xor_sync(0xffffffffu, acc, o);
    if (lane == 0) s2[row] = acc;
}

// ---------------------------------------------------------------------------
// C[M,N] = A[M,K] @ B[N,K]^T (+bias). A,B row-major K-contiguous, tf32-exact.
// Block 128x128x32, 256 thr, warp grid 2x4, warp tile 64x32.
// cp.async 3-stage ring, ldmatrix x4 fragments, XOR swizzle.
// biasMode: 0 none, 1 col bias[n], 2 row bias[m]. roundOut: tf32-round stores.
// ---------------------------------------------------------------------------
#define TILE_B  16384
#define STAGE   (2 * TILE_B)
#define SMEM_BYTES (3 * STAGE)   // 98304

__global__ __launch_bounds__(256, 2) void tgemm_nt(
    const float* __restrict__ A, const float* __restrict__ Bm,
    const float* __restrict__ bias, float* __restrict__ C,
    int K, int Ntot, long sA, long sB, long sC, int biasMode, int roundOut)
{
    extern __shared__ char smem[];
    const uint32_t sb = s2u(smem);

    const int tid  = threadIdx.x;
    const int lane = tid & 31;
    const int wid  = tid >> 5;
    const int wm   = (wid >> 2) * 64;
    const int wn   = (wid & 3) * 32;
    const int gid  = lane >> 2;
    const int tig  = lane & 3;

    const float* Ab = A  + (size_t)blockIdx.z * sA + (size_t)blockIdx.y * 128 * K;
    const float* Bb = Bm + (size_t)blockIdx.z * sB + (size_t)blockIdx.x * 128 * K;
    float*       Cb = C  + (size_t)blockIdx.z * sC;

    const int crow  = tid >> 1;
    const int cbase = (tid & 1) * 4;
    const int nkt   = K / 32;

    auto issue = [&](int t) {
        const int s = t % 3;
        const uint32_t As = sb + s * STAGE;
        const uint32_t Bs = As + TILE_B;
        const float* ga = Ab + (size_t)crow * K + t * 32 + cbase * 4;
        const float* gb = Bb + (size_t)crow * K + t * 32 + cbase * 4;
        const uint32_t arow = As + (uint32_t)crow * 128;
        const uint32_t brow = Bs + (uint32_t)crow * 128;
        const int r7 = crow & 7;
        #pragma unroll
        for (int i = 0; i < 4; i++) {
            const uint32_t off = (uint32_t)(((cbase + i) ^ r7) * 16);
            cp16(arow + off, ga + i * 4);
            cp16(brow + off, gb + i * 4);
        }
        CP_COMMIT();
    };

    issue(0); issue(1);

    float acc[4][4][4];
    #pragma unroll
    for (int mi = 0; mi < 4; mi++)
        #pragma unroll
        for (int nj = 0; nj < 4; nj++)
            #pragma unroll
            for (int r = 0; r < 4; r++) acc[mi][nj][r] = 0.f;

    const int la15 = lane & 15;
    const int lahi = lane >> 4;
    const int lbrow = ((lane >> 4) * 8) + (lane & 7);
    const int lbhi  = (lane >> 3) & 1;

    for (int t = 0; t < nkt; t++) {
        const uint32_t As = sb + (t % 3) * STAGE;
        const uint32_t Bs = As + TILE_B;

        CP_WAIT1();
        __syncthreads();
        if (t + 2 < nkt) issue(t + 2);

        #pragma unroll
        for (int kk = 0; kk < 4; kk++) {
            unsigned a[4][4], bq[2][4];
            #pragma unroll
            for (int mi = 0; mi < 4; mi++) {
                const int rowA = wm + mi * 16 + la15;
                const uint32_t addr = As + (uint32_t)rowA * 128
                    + (uint32_t)((((kk * 2) + lahi) ^ (rowA & 7)) * 16);
                ldsm_x4(a[mi], addr);
            }
            #pragma unroll
            for (int p = 0; p < 2; p++) {
                const int rowB = wn + p * 16 + lbrow;
                const uint32_t addr = Bs + (uint32_t)rowB * 128
                    + (uint32_t)((((kk * 2) + lbhi) ^ (rowB & 7)) * 16);
                ldsm_x4(bq[p], addr);
            }
            #pragma unroll
            for (int mi = 0; mi < 4; mi++)
                #pragma unroll
                for (int nj = 0; nj < 4; nj++)
                    mma_tf32(acc[mi][nj], a[mi][0], a[mi][1], a[mi][2], a[mi][3],
                             bq[nj >> 1][(nj & 1) * 2], bq[nj >> 1][(nj & 1) * 2 + 1]);
        }
    }
    CP_WAIT0();

    // ---- epilogue ----
    #pragma unroll
    for (int mi = 0; mi < 4; mi++) {
        const int row0 = blockIdx.y * 128 + wm + mi * 16 + gid;
        float rb0 = (biasMode == 2) ? __ldg(bias + row0)     : 0.f;
        float rb1 = (biasMode == 2) ? __ldg(bias + row0 + 8) : 0.f;
        #pragma unroll
        for (int nj = 0; nj < 4; nj++) {
            const int col = blockIdx.x * 128 + wn + nj * 8 + 2 * tig;
            float c0 = acc[mi][nj][0], c1 = acc[mi][nj][1];
            float c2 = acc[mi][nj][2], c3 = acc[mi][nj][3];
            if (biasMode == 1) {
                float b0 = __ldg(bias + col), b1 = __ldg(bias + col + 1);
                c0 += b0; c1 += b1; c2 += b0; c3 += b1;
            } else if (biasMode == 2) {
                c0 += rb0; c1 += rb0; c2 += rb1; c3 += rb1;
            }
            if (roundOut) {
                c0 = tf32r(c0); c1 = tf32r(c1); c2 = tf32r(c2); c3 = tf32r(c3);
            }
            *(float2*)(Cb + (size_t)row0 * Ntot + col)       = make_float2(c0, c1);
            *(float2*)(Cb + (size_t)(row0 + 8) * Ntot + col) = make_float2(c2, c3);
        }
    }
}

// ---------------------------------------------------------------------------
// In-place scaled softmax over rows of 512 with additive col bias s2[b,l];
// outputs tf32-rounded.
// ---------------------------------------------------------------------------
__global__ __launch_bounds__(256) void softmax_rows(
    float* __restrict__ S, const float* __restrict__ s2, float scale)
{
    const int row  = blockIdx.x * 8 + (threadIdx.x >> 5);
    const int lane = threadIdx.x & 31;
    const int b    = row >> 10;              // row = b*NQ + n
    float4* r4 = (float4*)(S + (size_t)row * LSEQ) + lane;
    const float4* b4 = (const float4*)(s2 + (size_t)b * LSEQ) + lane;

    float4 v[4];
    #pragma unroll
    for (int i = 0; i < 4; i++) {
        v[i] = r4[32 * i];
        float4 w = __ldg(b4 + 32 * i);
        v[i].x = (v[i].x + w.x) * scale; v[i].y = (v[i].y + w.y) * scale;
        v[i].z = (v[i].z + w.z) * scale; v[i].w = (v[i].w + w.w) * scale;
    }
    float mx = -3.4e38f;
    #pragma unroll
    for (int i = 0; i < 4; i++)
        mx = fmaxf(mx, fmaxf(fmaxf(v[i].x, v[i].y), fmaxf(v[i].z, v[i].w)));
    #pragma unroll
    for (int o = 16; o > 0; o >>= 1)
        mx = fmaxf(mx, __shfl_xor_sync(0xffffffffu, mx, o));
    float sum = 0.f;
    #pragma unroll
    for (int i = 0; i < 4; i++) {
        v[i].x = __expf(v[i].x - mx); v[i].y = __expf(v[i].y - mx);
        v[i].z = __expf(v[i].z - mx); v[i].w = __expf(v[i].w - mx);
        sum += v[i].x + v[i].y + v[i].z + v[i].w;
    }
    #pragma unroll
    for (int o = 16; o > 0; o >>= 1)
        sum += __shfl_xor_sync(0xffffffffu, sum, o);
    const float inv = 1.0f / sum;
    #pragma unroll
    for (int i = 0; i < 4; i++) {
        v[i].x = tf32r(v[i].x * inv); v[i].y = tf32r(v[i].y * inv);
        v[i].z = tf32r(v[i].z * inv); v[i].w = tf32r(v[i].w * inv);
        r4[32 * i] = v[i];
    }
}

extern "C" void kernel_launch(void* const* d_in, const int* in_sizes, int n_in,
                              void* d_out, int out_size)
{
    const float* q   = (const float*)d_in[0];
    const float* k   = (const float*)d_in[1];
    const float* v   = (const float*)d_in[2];
    const float* q_w = (const float*)d_in[3];
    const float* q_b = (const float*)d_in[4];
    const float* k_w = (const float*)d_in[5];
    const float* v_w = (const float*)d_in[7];
    const float* v_b = (const float*)d_in[8];
    float* out = (float*)d_out;

    float *rq, *rk, *rv, *rwv, *rwqt, *rwkt, *gt, *w2, *s2, *qg, *vpt, *s;
    cudaGetSymbolAddress((void**)&rq,   g_rq);
    cudaGetSymbolAddress((void**)&rk,   g_rk);
    cudaGetSymbolAddress((void**)&rv,   g_rv);
    cudaGetSymbolAddress((void**)&rwv,  g_rwv);
    cudaGetSymbolAddress((void**)&rwqt, g_rwqt);
    cudaGetSymbolAddress((void**)&rwkt, g_rwkt);
    cudaGetSymbolAddress((void**)&gt,   g_gt);
    cudaGetSymbolAddress((void**)&w2,   g_w2);
    cudaGetSymbolAddress((void**)&s2,   g_s2);
    cudaGetSymbolAddress((void**)&qg,   g_qg);
    cudaGetSymbolAddress((void**)&vpt,  g_vpt);
    cudaGetSymbolAddress((void**)&s,    g_s);

    cudaFuncSetAttribute(tgemm_nt, cudaFuncAttributeMaxDynamicSharedMemorySize, SMEM_BYTES);

    const int nq4 = BATCH * NQ * DIM / 4;
    const int nk4 = BATCH * LSEQ * DIM / 4;

    // 0: round q,k,v
    round3_tf32<<<(nq4 + 2 * nk4) / 256, 256>>>(q, rq, k, rk, v, rv, nq4, nk4);
    // 1: transpose+round q_w -> rwqt, k_w -> rwkt; round v_w -> rwv
    transpose_round<<<dim3(24, 24, 3), dim3(32, 8)>>>(q_w, rwqt, k_w, rwkt, v_w, rwv);
    // 2: w2[c] = sum_d bq[d] k_w[d,c]
    compute_w2<<<DIM / 32, 256>>>(k_w, q_b, w2);
    // 3: Gt[c'][c] = sum_d kw[d,c'] qw[d,c]  (NT: A=rwkt, B=rwqt)
    tgemm_nt<<<dim3(DIM / 128, DIM / 128, 1), 256, SMEM_BYTES>>>(
        rwkt, rwqt, nullptr, gt, DIM, DIM, 0, 0, 0, 0, 1);
    // 4: s2[b,l] = rk[b,l,:] . w2
    compute_s2<<<(BATCH * LSEQ) / 8, 256>>>(rk, w2, s2);
    // 5 (ncu target): qG[n,c'] = sum_c rq[n,c] Gt[c',c]  (M=32768, N=768)
    tgemm_nt<<<dim3(DIM / 128, (BATCH * NQ) / 128, 1), 256, SMEM_BYTES>>>(
        rq, gt, nullptr, qg, DIM, DIM, 0, 0, 0, 0, 1);
    // 6: vpT[b,d,l] = vw @ rv[b]^T + vb[d]  (M=768, N=512, row bias)
    tgemm_nt<<<dim3(LSEQ / 128, DIM / 128, BATCH), 256, SMEM_BYTES>>>(
        rwv, rv, v_b, vpt, DIM, LSEQ,
        0, (long)LSEQ * DIM, (long)DIM * LSEQ, 2, 1);
    // 7: S[b] = qG[b] @ rk[b]^T   (M=1024, N=512, K=768)
    tgemm_nt<<<dim3(LSEQ / 128, NQ / 128, BATCH), 256, SMEM_BYTES>>>(
        qg, rk, nullptr, s, DIM, LSEQ,
        (long)NQ * DIM, (long)LSEQ * DIM, (long)NQ * LSEQ, 0, 0);
    // 8: softmax((S + s2) * scale), tf32-rounded output
    softmax_rows<<<(BATCH * NQ) / 8, 256>>>(s, s2, 0.03608439182435161f);
    // 9: out[b] = P[b] @ vpT[b]^T   (M=1024, N=768, K=512)
    tgemm_nt<<<dim3(DIM / 128, NQ / 128, BATCH), 256, SMEM_BYTES>>>(
        s, vpt, nullptr, out, LSEQ, DIM,
        (long)NQ * LSEQ, (long)DIM * LSEQ, (long)NQ * DIM, 0, 0);
}

// round 9
// speedup vs baseline: 1.6733x; 1.0944x over previous
#include <cuda_runtime.h>
#include <cstdint>
#include <cstddef>

#define BATCH 32
#define NQ    1024
#define LSEQ  512
#define DIM   768
#define HB    16   // half-batch

// Scratch (device globals)
__device__ float g_rq  [(size_t)BATCH * NQ   * DIM ];
__device__ float g_rk  [(size_t)BATCH * LSEQ * DIM ];
__device__ float g_rv  [(size_t)BATCH * LSEQ * DIM ];
__device__ float g_rwv [DIM * DIM];
__device__ float g_rwqt[DIM * DIM];
__device__ float g_rwkt[DIM * DIM];
__device__ float g_gt  [DIM * DIM];
__device__ float g_w2  [DIM];
__device__ float g_s2  [(size_t)BATCH * LSEQ];
__device__ float g_qg  [(size_t)BATCH * NQ   * DIM ];
__device__ float g_vpt [(size_t)BATCH * DIM  * LSEQ];
__device__ float g_s   [(size_t)BATCH * NQ   * LSEQ];

__device__ __forceinline__ float tf32r(float x) {
    unsigned r; asm("cvt.rna.tf32.f32 %0,%1;" : "=r"(r) : "f"(x));
    return __uint_as_float(r);
}

__device__ __forceinline__ void mma_tf32(float c[4],
    unsigned a0, unsigned a1, unsigned a2, unsigned a3,
    unsigned b0, unsigned b1)
{
    asm("mma.sync.aligned.m16n8k8.row.col.f32.tf32.tf32.f32 "
        "{%0,%1,%2,%3},{%4,%5,%6,%7},{%8,%9},{%0,%1,%2,%3};"
        : "+f"(c[0]), "+f"(c[1]), "+f"(c[2]), "+f"(c[3])
        : "r"(a0), "r"(a1), "r"(a2), "r"(a3), "r"(b0), "r"(b1));
}

__device__ __forceinline__ void ldsm_x4(unsigned r[4], uint32_t addr) {
    asm volatile("ldmatrix.sync.aligned.m8n8.x4.shared.b16 {%0,%1,%2,%3}, [%4];"
        : "=r"(r[0]), "=r"(r[1]), "=r"(r[2]), "=r"(r[3]) : "r"(addr));
}

__device__ __forceinline__ void cp16(uint32_t dst, const void* src) {
    asm volatile("cp.async.cg.shared.global [%0], [%1], 16;" :: "r"(dst), "l"(src));
}
#define CP_COMMIT() asm volatile("cp.async.commit_group;" ::: "memory")
#define CP_WAIT1()  asm volatile("cp.async.wait_group 1;" ::: "memory")
#define CP_WAIT0()  asm volatile("cp.async.wait_group 0;" ::: "memory")

__device__ __forceinline__ uint32_t s2u(const void* p) {
    uint32_t a;
    asm("{ .reg .u64 t; cvta.to.shared.u64 t, %1; cvt.u32.u64 %0, t; }"
        : "=r"(a) : "l"(p));
    return a;
}

// ---------------------------------------------------------------------------
__global__ __launch_bounds__(256) void round3_tf32(
    const float* __restrict__ s0, float* __restrict__ d0,
    const float* __restrict__ s1, float* __restrict__ d1,
    const float* __restrict__ s2, float* __restrict__ d2,
    int a4, int b4)
{
    int i = blockIdx.x * 256 + threadIdx.x;
    const float* src; float* dst; int j;
    if (i < a4)            { src = s0; dst = d0; j = i; }
    else if (i < a4 + b4)  { src = s1; dst = d1; j = i - a4; }
    else                   { src = s2; dst = d2; j = i - a4 - b4; }
    float4 v = ((const float4*)src)[j];
    v.x = tf32r(v.x); v.y = tf32r(v.y); v.z = tf32r(v.z); v.w = tf32r(v.w);
    ((float4*)dst)[j] = v;
}

// ---------------------------------------------------------------------------
// z=0: q_w -> rwqt transposed+rounded; z=1: k_w -> rwkt; z=2: v_w -> rwv copy.
// ---------------------------------------------------------------------------
__global__ __launch_bounds__(256) void transpose_round(
    const float* __restrict__ qw, float* __restrict__ dqt,
    const float* __restrict__ kw, float* __restrict__ dkt,
    const float* __restrict__ vw, float* __restrict__ dv)
{
    const int tx = threadIdx.x, ty = threadIdx.y;
    const int x = blockIdx.x * 32 + tx;
    const int y = blockIdx.y * 32 + ty;

    if (blockIdx.z == 2) {
        #pragma unroll
        for (int i = 0; i < 32; i += 8)
            dv[(size_t)(y + i) * DIM + x] = tf32r(vw[(size_t)(y + i) * DIM + x]);
        return;
    }

    __shared__ float tile[32][33];
    const float* src = blockIdx.z ? kw : qw;
    float*       dst = blockIdx.z ? dkt : dqt;
    #pragma unroll
    for (int i = 0; i < 32; i += 8)
        tile[ty + i][tx] = src[(size_t)(y + i) * DIM + x];
    __syncthreads();
    const int xo = blockIdx.y * 32 + tx;
    const int yo = blockIdx.x * 32 + ty;
    #pragma unroll
    for (int i = 0; i < 32; i += 8)
        dst[(size_t)(yo + i) * DIM + xo] = tf32r(tile[tx][ty + i]);
}

// ---------------------------------------------------------------------------
__global__ __launch_bounds__(256) void compute_w2(
    const float* __restrict__ kw, const float* __restrict__ bq,
    float* __restrict__ w2)
{
    __shared__ float part[8][32];
    const int cl = threadIdx.x & 31;
    const int dg = threadIdx.x >> 5;
    const int c  = blockIdx.x * 32 + cl;
    float acc = 0.f;
    const int d0 = dg * 96;
    #pragma unroll 8
    for (int d = d0; d < d0 + 96; d++)
        acc += __ldg(bq + d) * __ldg(kw + (size_t)d * DIM + c);
    part[dg][cl] = acc;
    __syncthreads();
    if (dg == 0) {
        float s = 0.f;
        #pragma unroll
        for (int i = 0; i < 8; i++) s += part[i][cl];
        w2[c] = s;
    }
}

// ---------------------------------------------------------------------------
__global__ __launch_bounds__(256) void compute_s2(
    const float* __restrict__ rk, const float* __restrict__ w2,
    float* __restrict__ s2)
{
    const int row  = blockIdx.x * 8 + (threadIdx.x >> 5);
    const int lane = threadIdx.x & 31;
    const float4* kr = (const float4*)(rk + (size_t)row * DIM);
    const float4* w4 = (const float4*)w2;
    float acc = 0.f;
    #pragma unroll
    for (int i = 0; i < 6; i++) {
        float4 a = kr[lane + 32 * i];
        float4 b = __ldg(w4 + lane + 32 * i);
        acc += a.x * b.x + a.y * b.y + a.z * b.z + a.w * b.w;
    }
    #pragma unroll
    for (int o = 16; o > 0; o >>= 1)
        acc += __shfl_xor_sync(0xffffffffu, acc, o);
    if (lane == 0) s2[row] = acc;
}

// ---------------------------------------------------------------------------
// C[M,N] = A[M,K] @ B[N,K]^T (+bias). See R6 notes. UNCHANGED (proven).
// ---------------------------------------------------------------------------
#define TILE_B  16384
#define STAGE   (2 * TILE_B)
#define SMEM_BYTES (3 * STAGE)

__global__ __launch_bounds__(256, 2) void tgemm_nt(
    const float* __restrict__ A, const float* __restrict__ Bm,
    const float* __restrict__ bias, float* __restrict__ C,
    int K, int Ntot, long sA, long sB, long sC, int biasMode, int roundOut)
{
    extern __shared__ char smem[];
    const uint32_t sb = s2u(smem);

    const int tid  = threadIdx.x;
    const int lane = tid & 31;
    const int wid  = tid >> 5;
    const int wm   = (wid >> 2) * 64;
    const int wn   = (wid & 3) * 32;
    const int gid  = lane >> 2;
    const int tig  = lane & 3;

    const float* Ab = A  + (size_t)blockIdx.z * sA + (size_t)blockIdx.y * 128 * K;
    const float* Bb = Bm + (size_t)blockIdx.z * sB + (size_t)blockIdx.x * 128 * K;
    float*       Cb = C  + (size_t)blockIdx.z * sC;

    const int crow  = tid >> 1;
    const int cbase = (tid & 1) * 4;
    const int nkt   = K / 32;

    auto issue = [&](int t) {
        const int s = t % 3;
        const uint32_t As = sb + s * STAGE;
        const uint32_t Bs = As + TILE_B;
        const float* ga = Ab + (size_t)crow * K + t * 32 + cbase * 4;
        const float* gb = Bb + (size_t)crow * K + t * 32 + cbase * 4;
        const uint32_t arow = As + (uint32_t)crow * 128;
        const uint32_t brow = Bs + (uint32_t)crow * 128;
        const int r7 = crow & 7;
        #pragma unroll
        for (int i = 0; i < 4; i++) {
            const uint32_t off = (uint32_t)(((cbase + i) ^ r7) * 16);
            cp16(arow + off, ga + i * 4);
            cp16(brow + off, gb + i * 4);
        }
        CP_COMMIT();
    };

    issue(0); issue(1);

    float acc[4][4][4];
    #pragma unroll
    for (int mi = 0; mi < 4; mi++)
        #pragma unroll
        for (int nj = 0; nj < 4; nj++)
            #pragma unroll
            for (int r = 0; r < 4; r++) acc[mi][nj][r] = 0.f;

    const int la15 = lane & 15;
    const int lahi = lane >> 4;
    const int lbrow = ((lane >> 4) * 8) + (lane & 7);
    const int lbhi  = (lane >> 3) & 1;

    for (int t = 0; t < nkt; t++) {
        const uint32_t As = sb + (t % 3) * STAGE;
        const uint32_t Bs = As + TILE_B;

        CP_WAIT1();
        __syncthreads();
        if (t + 2 < nkt) issue(t + 2);

        #pragma unroll
        for (int kk = 0; kk < 4; kk++) {
            unsigned a[4][4], bq[2][4];
            #pragma unroll
            for (int mi = 0; mi < 4; mi++) {
                const int rowA = wm + mi * 16 + la15;
                const uint32_t addr = As + (uint32_t)rowA * 128
                    + (uint32_t)((((kk * 2) + lahi) ^ (rowA & 7)) * 16);
                ldsm_x4(a[mi], addr);
            }
            #pragma unroll
            for (int p = 0; p < 2; p++) {
                const int rowB = wn + p * 16 + lbrow;
                const uint32_t addr = Bs + (uint32_t)rowB * 128
                    + (uint32_t)((((kk * 2) + lbhi) ^ (rowB & 7)) * 16);
                ldsm_x4(bq[p], addr);
            }
            #pragma unroll
            for (int mi = 0; mi < 4; mi++)
                #pragma unroll
                for (int nj = 0; nj < 4; nj++)
                    mma_tf32(acc[mi][nj], a[mi][0], a[mi][1], a[mi][2], a[mi][3],
                             bq[nj >> 1][(nj & 1) * 2], bq[nj >> 1][(nj & 1) * 2 + 1]);
        }
    }
    CP_WAIT0();

    #pragma unroll
    for (int mi = 0; mi < 4; mi++) {
        const int row0 = blockIdx.y * 128 + wm + mi * 16 + gid;
        float rb0 = (biasMode == 2) ? __ldg(bias + row0)     : 0.f;
        float rb1 = (biasMode == 2) ? __ldg(bias + row0 + 8) : 0.f;
        #pragma unroll
        for (int nj = 0; nj < 4; nj++) {
            const int col = blockIdx.x * 128 + wn + nj * 8 + 2 * tig;
            float c0 = acc[mi][nj][0], c1 = acc[mi][nj][1];
            float c2 = acc[mi][nj][2], c3 = acc[mi][nj][3];
            if (biasMode == 1) {
                float b0 = __ldg(bias + col), b1 = __ldg(bias + col + 1);
                c0 += b0; c1 += b1; c2 += b0; c3 += b1;
            } else if (biasMode == 2) {
                c0 += rb0; c1 += rb0; c2 += rb1; c3 += rb1;
            }
            if (roundOut) {
                c0 = tf32r(c0); c1 = tf32r(c1); c2 = tf32r(c2); c3 = tf32r(c3);
            }
            *(float2*)(Cb + (size_t)row0 * Ntot + col)       = make_float2(c0, c1);
            *(float2*)(Cb + (size_t)(row0 + 8) * Ntot + col) = make_float2(c2, c3);
        }
    }
}

// ---------------------------------------------------------------------------
__global__ __launch_bounds__(256) void softmax_rows(
    float* __restrict__ S, const float* __restrict__ s2, float scale)
{
    const int row  = blockIdx.x * 8 + (threadIdx.x >> 5);
    const int lane = threadIdx.x & 31;
    const int b    = row >> 10;
    float4* r4 = (float4*)(S + (size_t)row * LSEQ) + lane;
    const float4* b4 = (const float4*)(s2 + (size_t)b * LSEQ) + lane;

    float4 v[4];
    #pragma unroll
    for (int i = 0; i < 4; i++) {
        v[i] = r4[32 * i];
        float4 w = __ldg(b4 + 32 * i);
        v[i].x = (v[i].x + w.x) * scale; v[i].y = (v[i].y + w.y) * scale;
        v[i].z = (v[i].z + w.z) * scale; v[i].w = (v[i].w + w.w) * scale;
    }
    float mx = -3.4e38f;
    #pragma unroll
    for (int i = 0; i < 4; i++)
        mx = fmaxf(mx, fmaxf(fmaxf(v[i].x, v[i].y), fmaxf(v[i].z, v[i].w)));
    #pragma unroll
    for (int o = 16; o > 0; o >>= 1)
        mx = fmaxf(mx, __shfl_xor_sync(0xffffffffu, mx, o));
    float sum = 0.f;
    #pragma unroll
    for (int i = 0; i < 4; i++) {
        v[i].x = __expf(v[i].x - mx); v[i].y = __expf(v[i].y - mx);
        v[i].z = __expf(v[i].z - mx); v[i].w = __expf(v[i].w - mx);
        sum += v[i].x + v[i].y + v[i].z + v[i].w;
    }
    #pragma unroll
    for (int o = 16; o > 0; o >>= 1)
        sum += __shfl_xor_sync(0xffffffffu, sum, o);
    const float inv = 1.0f / sum;
    #pragma unroll
    for (int i = 0; i < 4; i++) {
        v[i].x = tf32r(v[i].x * inv); v[i].y = tf32r(v[i].y * inv);
        v[i].z = tf32r(v[i].z * inv); v[i].w = tf32r(v[i].w * inv);
        r4[32 * i] = v[i];
    }
}

extern "C" void kernel_launch(void* const* d_in, const int* in_sizes, int n_in,
                              void* d_out, int out_size)
{
    const float* q   = (const float*)d_in[0];
    const float* k   = (const float*)d_in[1];
    const float* v   = (const float*)d_in[2];
    const float* q_w = (const float*)d_in[3];
    const float* q_b = (const float*)d_in[4];
    const float* k_w = (const float*)d_in[5];
    const float* v_w = (const float*)d_in[7];
    const float* v_b = (const float*)d_in[8];
    float* out = (float*)d_out;

    float *rq, *rk, *rv, *rwv, *rwqt, *rwkt, *gt, *w2, *s2p, *qg, *vpt, *s;
    cudaGetSymbolAddress((void**)&rq,   g_rq);
    cudaGetSymbolAddress((void**)&rk,   g_rk);
    cudaGetSymbolAddress((void**)&rv,   g_rv);
    cudaGetSymbolAddress((void**)&rwv,  g_rwv);
    cudaGetSymbolAddress((void**)&rwqt, g_rwqt);
    cudaGetSymbolAddress((void**)&rwkt, g_rwkt);
    cudaGetSymbolAddress((void**)&gt,   g_gt);
    cudaGetSymbolAddress((void**)&w2,   g_w2);
    cudaGetSymbolAddress((void**)&s2p,  g_s2);
    cudaGetSymbolAddress((void**)&qg,   g_qg);
    cudaGetSymbolAddress((void**)&vpt,  g_vpt);
    cudaGetSymbolAddress((void**)&s,    g_s);

    // Streams/events created once on the first (uncaptured) correctness call.
    static cudaStream_t s1 = nullptr, s2 = nullptr, s3 = nullptr;
    static cudaEvent_t eFork, eRound3, eGt, eS2, eVpt, eQg, eDone;
    if (!s1) {
        cudaStreamCreateWithFlags(&s1, cudaStreamNonBlocking);
        cudaStreamCreateWithFlags(&s2, cudaStreamNonBlocking);
        cudaStreamCreateWithFlags(&s3, cudaStreamNonBlocking);
        cudaEventCreateWithFlags(&eFork,   cudaEventDisableTiming);
        cudaEventCreateWithFlags(&eRound3, cudaEventDisableTiming);
        cudaEventCreateWithFlags(&eGt,     cudaEventDisableTiming);
        cudaEventCreateWithFlags(&eS2,     cudaEventDisableTiming);
        cudaEventCreateWithFlags(&eVpt,    cudaEventDisableTiming);
        cudaEventCreateWithFlags(&eQg,     cudaEventDisableTiming);
        cudaEventCreateWithFlags(&eDone,   cudaEventDisableTiming);
        cudaFuncSetAttribute(tgemm_nt, cudaFuncAttributeMaxDynamicSharedMemorySize, SMEM_BYTES);
    }

    const int nq4 = BATCH * NQ * DIM / 4;
    const int nk4 = BATCH * LSEQ * DIM / 4;
    const float SCALE = 0.03608439182435161f;

    // ---- fork ----
    cudaEventRecord(eFork, 0);
    cudaStreamWaitEvent(s1, eFork, 0);
    cudaStreamWaitEvent(s2, eFork, 0);
    cudaStreamWaitEvent(s3, eFork, 0);

    // s0: round q,k,v (big bandwidth pass)
    round3_tf32<<<(nq4 + 2 * nk4) / 256, 256, 0, 0>>>(q, rq, k, rk, v, rv, nq4, nk4);
    cudaEventRecord(eRound3, 0);

    // s1: weight transpose/round, then Gt, then vpt (after round3)
    transpose_round<<<dim3(24, 24, 3), dim3(32, 8), 0, s1>>>(q_w, rwqt, k_w, rwkt, v_w, rwv);
    tgemm_nt<<<dim3(DIM / 128, DIM / 128, 1), 256, SMEM_BYTES, s1>>>(
        rwkt, rwqt, nullptr, gt, DIM, DIM, 0, 0, 0, 0, 1);
    cudaEventRecord(eGt, s1);
    cudaStreamWaitEvent(s1, eRound3, 0);
    tgemm_nt<<<dim3(LSEQ / 128, DIM / 128, BATCH), 256, SMEM_BYTES, s1>>>(
        rwv, rv, v_b, vpt, DIM, LSEQ,
        0, (long)LSEQ * DIM, (long)DIM * LSEQ, 2, 1);
    cudaEventRecord(eVpt, s1);

    // s2: w2, then s2 (after round3)
    compute_w2<<<DIM / 32, 256, 0, s2>>>(k_w, q_b, w2);
    cudaStreamWaitEvent(s2, eRound3, 0);
    compute_s2<<<(BATCH * LSEQ) / 8, 256, 0, s2>>>(rk, w2, s2p);
    cudaEventRecord(eS2, s2);

    // s0: qG = rq @ Gt^T (needs Gt)
    cudaStreamWaitEvent(0, eGt, 0);
    tgemm_nt<<<dim3(DIM / 128, (BATCH * NQ) / 128, 1), 256, SMEM_BYTES, 0>>>(
        rq, gt, nullptr, qg, DIM, DIM, 0, 0, 0, 0, 1);
    cudaEventRecord(eQg, 0);
    cudaStreamWaitEvent(s3, eQg, 0);

    // ---- batch halves: s0 handles b 0..15, s3 handles b 16..31 ----
    const size_t oQG  = (size_t)HB * NQ * DIM;
    const size_t oRK  = (size_t)HB * LSEQ * DIM;
    const size_t oS   = (size_t)HB * NQ * LSEQ;
    const size_t oS2  = (size_t)HB * LSEQ;
    const size_t oVPT = (size_t)HB * DIM * LSEQ;
    const size_t oOUT = (size_t)HB * NQ * DIM;

    // S halves
    tgemm_nt<<<dim3(LSEQ / 128, NQ / 128, HB), 256, SMEM_BYTES, 0>>>(
        qg, rk, nullptr, s, DIM, LSEQ,
        (long)NQ * DIM, (long)LSEQ * DIM, (long)NQ * LSEQ, 0, 0);
    tgemm_nt<<<dim3(LSEQ / 128, NQ / 128, HB), 256, SMEM_BYTES, s3>>>(
        qg + oQG, rk + oRK, nullptr, s + oS, DIM, LSEQ,
        (long)NQ * DIM, (long)LSEQ * DIM, (long)NQ * LSEQ, 0, 0);

    // softmax halves (need s2)
    cudaStreamWaitEvent(0, eS2, 0);
    softmax_rows<<<(HB * NQ) / 8, 256, 0, 0>>>(s, s2p, SCALE);
    cudaStreamWaitEvent(s3, eS2, 0);
    softmax_rows<<<(HB * NQ) / 8, 256, 0, s3>>>(s + oS, s2p + oS2, SCALE);

    // out halves (need vpt)
    cudaStreamWaitEvent(0, eVpt, 0);
    tgemm_nt<<<dim3(DIM / 128, NQ / 128, HB), 256, SMEM_BYTES, 0>>>(
        s, vpt, nullptr, out, LSEQ, DIM,
        (long)NQ * LSEQ, (long)DIM * LSEQ, (long)NQ * DIM, 0, 0);
    cudaStreamWaitEvent(s3, eVpt, 0);
    tgemm_nt<<<dim3(DIM / 128, NQ / 128, HB), 256, SMEM_BYTES, s3>>>(
        s + oS, vpt + oVPT, nullptr, out + oOUT, LSEQ, DIM,
        (long)NQ * LSEQ, (long)DIM * LSEQ, (long)NQ * DIM, 0, 0);

    // ---- join ----
    cudaEventRecord(eDone, s3);
    cudaStreamWaitEvent(0, eDone, 0);
}

// round 10
// speedup vs baseline: 2.9742x; 1.7775x over previous
#include <cuda_runtime.h>
#include <cuda_fp16.h>
#include <cstdint>
#include <cstddef>

#define BATCH 32
#define NQ    1024
#define LSEQ  512
#define DIM   768
#define HB    16   // half-batch

// Scratch (device globals) — GEMM operands are fp16 now
__device__ __half g_rq  [(size_t)BATCH * NQ   * DIM ];
__device__ __half g_rk  [(size_t)BATCH * LSEQ * DIM ];
__device__ __half g_rv  [(size_t)BATCH * LSEQ * DIM ];
__device__ __half g_rwv [DIM * DIM];
__device__ __half g_rwqt[DIM * DIM];
__device__ __half g_rwkt[DIM * DIM];
__device__ __half g_gt  [DIM * DIM];
__device__ float  g_w2  [DIM];
__device__ float  g_s2  [(size_t)BATCH * LSEQ];
__device__ __half g_qg  [(size_t)BATCH * NQ   * DIM ];
__device__ __half g_vpt [(size_t)BATCH * DIM  * LSEQ];
__device__ float  g_s   [(size_t)BATCH * NQ   * LSEQ];   // raw scores (fp32)
__device__ __half g_p   [(size_t)BATCH * NQ   * LSEQ];   // softmax probs (fp16)

__device__ __forceinline__ void mma_f16(float c[4],
    unsigned a0, unsigned a1, unsigned a2, unsigned a3,
    unsigned b0, unsigned b1)
{
    asm("mma.sync.aligned.m16n8k16.row.col.f32.f16.f16.f32 "
        "{%0,%1,%2,%3},{%4,%5,%6,%7},{%8,%9},{%0,%1,%2,%3};"
        : "+f"(c[0]), "+f"(c[1]), "+f"(c[2]), "+f"(c[3])
        : "r"(a0), "r"(a1), "r"(a2), "r"(a3), "r"(b0), "r"(b1));
}

__device__ __forceinline__ void ldsm_x4(unsigned r[4], uint32_t addr) {
    asm volatile("ldmatrix.sync.aligned.m8n8.x4.shared.b16 {%0,%1,%2,%3}, [%4];"
        : "=r"(r[0]), "=r"(r[1]), "=r"(r[2]), "=r"(r[3]) : "r"(addr));
}

__device__ __forceinline__ void cp16(uint32_t dst, const void* src) {
    asm volatile("cp.async.cg.shared.global [%0], [%1], 16;" :: "r"(dst), "l"(src));
}
#define CP_COMMIT() asm volatile("cp.async.commit_group;" ::: "memory")
#define CP_WAIT1()  asm volatile("cp.async.wait_group 1;" ::: "memory")
#define CP_WAIT0()  asm volatile("cp.async.wait_group 0;" ::: "memory")

__device__ __forceinline__ uint32_t s2u(const void* p) {
    uint32_t a;
    asm("{ .reg .u64 t; cvta.to.shared.u64 t, %1; cvt.u32.u64 %0, t; }"
        : "=r"(a) : "l"(p));
    return a;
}

__device__ __forceinline__ unsigned h2u(__half2 h) {
    return *(unsigned*)&h;
}

// ---------------------------------------------------------------------------
// 3-segment fp32 -> fp16 rounding (rn)
// ---------------------------------------------------------------------------
__global__ __launch_bounds__(256) void round3_h(
    const float* __restrict__ s0, __half* __restrict__ d0,
    const float* __restrict__ s1, __half* __restrict__ d1,
    const float* __restrict__ s2, __half* __restrict__ d2,
    int a4, int b4)
{
    int i = blockIdx.x * 256 + threadIdx.x;
    const float* src; __half* dst; int j;
    if (i < a4)            { src = s0; dst = d0; j = i; }
    else if (i < a4 + b4)  { src = s1; dst = d1; j = i - a4; }
    else                   { src = s2; dst = d2; j = i - a4 - b4; }
    float4 v = ((const float4*)src)[j];
    uint2 u;
    u.x = h2u(__floats2half2_rn(v.x, v.y));
    u.y = h2u(__floats2half2_rn(v.z, v.w));
    ((uint2*)dst)[j] = u;
}

// ---------------------------------------------------------------------------
// z=0: q_w -> rwqt transposed+rounded; z=1: k_w -> rwkt; z=2: v_w -> rwv copy.
// ---------------------------------------------------------------------------
__global__ __launch_bounds__(256) void transpose_round(
    const float* __restrict__ qw, __half* __restrict__ dqt,
    const float* __restrict__ kw, __half* __restrict__ dkt,
    const float* __restrict__ vw, __half* __restrict__ dv)
{
    const int tx = threadIdx.x, ty = threadIdx.y;
    const int x = blockIdx.x * 32 + tx;
    const int y = blockIdx.y * 32 + ty;

    if (blockIdx.z == 2) {
        #pragma unroll
        for (int i = 0; i < 32; i += 8)
            dv[(size_t)(y + i) * DIM + x] = __float2half_rn(vw[(size_t)(y + i) * DIM + x]);
        return;
    }

    __shared__ float tile[32][33];
    const float* src = blockIdx.z ? kw : qw;
    __half*      dst = blockIdx.z ? dkt : dqt;
    #pragma unroll
    for (int i = 0; i < 32; i += 8)
        tile[ty + i][tx] = src[(size_t)(y + i) * DIM + x];
    __syncthreads();
    const int xo = blockIdx.y * 32 + tx;
    const int yo = blockIdx.x * 32 + ty;
    #pragma unroll
    for (int i = 0; i < 32; i += 8)
        dst[(size_t)(yo + i) * DIM + xo] = __float2half_rn(tile[tx][ty + i]);
}

// ---------------------------------------------------------------------------
__global__ __launch_bounds__(256) void compute_w2(
    const float* __restrict__ kw, const float* __restrict__ bq,
    float* __restrict__ w2)
{
    __shared__ float part[8][32];
    const int cl = threadIdx.x & 31;
    const int dg = threadIdx.x >> 5;
    const int c  = blockIdx.x * 32 + cl;
    float acc = 0.f;
    const int d0 = dg * 96;
    #pragma unroll 8
    for (int d = d0; d < d0 + 96; d++)
        acc += __ldg(bq + d) * __ldg(kw + (size_t)d * DIM + c);
    part[dg][cl] = acc;
    __syncthreads();
    if (dg == 0) {
        float s = 0.f;
        #pragma unroll
        for (int i = 0; i < 8; i++) s += part[i][cl];
        w2[c] = s;
    }
}

// ---------------------------------------------------------------------------
// s2[row] = rk[row,:] . w2   (rk fp16, w2 fp32), one warp per row
// ---------------------------------------------------------------------------
__global__ __launch_bounds__(256) void compute_s2(
    const __half* __restrict__ rk, const float* __restrict__ w2,
    float* __restrict__ s2)
{
    const int row  = blockIdx.x * 8 + (threadIdx.x >> 5);
    const int lane = threadIdx.x & 31;
    const uint4*  kr = (const uint4*)(rk + (size_t)row * DIM);   // 96 uint4 per row
    const float4* w4 = (const float4*)w2;
    float acc = 0.f;
    #pragma unroll
    for (int i = 0; i < 3; i++) {
        const int c = lane + 32 * i;          // 8-half chunk index
        uint4 u = kr[c];
        float4 wa = __ldg(w4 + 2 * c), wb = __ldg(w4 + 2 * c + 1);
        float2 f;
        f = __half22float2(*(__half2*)&u.x); acc += f.x * wa.x + f.y * wa.y;
        f = __half22float2(*(__half2*)&u.y); acc += f.x * wa.z + f.y * wa.w;
        f = __half22float2(*(__half2*)&u.z); acc += f.x * wb.x + f.y * wb.y;
        f = __half22float2(*(__half2*)&u.w); acc += f.x * wb.z + f.y * wb.w;
    }
    #pragma unroll
    for (int o = 16; o > 0; o >>= 1)
        acc += __shfl_xor_sync(0xffffffffu, acc, o);
    if (lane == 0) s2[row] = acc;
}

// ---------------------------------------------------------------------------
// C[M,N] = A[M,K] @ B[N,K]^T (+bias). A,B fp16 row-major K-contiguous.
// Block 128x128xK64, 256 thr, warp grid 2x4, warp tile 64x32.
// Rows of 64 halves = 128B, 8 x 16B chunks XOR-swizzled by (row&7).
// cp.async 3-stage ring; ldmatrix x4; mma m16n8k16 fp16, fp32 accum.
// biasMode: 0 none, 2 row bias[m]. halfOut: store fp16, else fp32.
// ---------------------------------------------------------------------------
#define TILE_B  16384
#define STAGE   (2 * TILE_B)
#define SMEM_BYTES (3 * STAGE)

__global__ __launch_bounds__(256, 2) void hgemm_nt(
    const __half* __restrict__ A, const __half* __restrict__ Bm,
    const float* __restrict__ bias, void* __restrict__ Cv,
    int K, int Ntot, long sA, long sB, long sC, int biasMode, int halfOut)
{
    extern __shared__ char smem[];
    const uint32_t sb = s2u(smem);

    const int tid  = threadIdx.x;
    const int lane = tid & 31;
    const int wid  = tid >> 5;
    const int wm   = (wid >> 2) * 64;
    const int wn   = (wid & 3) * 32;
    const int gid  = lane >> 2;
    const int tig  = lane & 3;

    const __half* Ab = A  + (size_t)blockIdx.z * sA + (size_t)blockIdx.y * 128 * K;
    const __half* Bb = Bm + (size_t)blockIdx.z * sB + (size_t)blockIdx.x * 128 * K;

    const int crow  = tid >> 1;          // copy row 0..127
    const int cbase = (tid & 1) * 4;     // chunk base 0 or 4
    const int nkt   = K / 64;            // 64 halves per tile row

    auto issue = [&](int t) {
        const int s = t % 3;
        const uint32_t As = sb + s * STAGE;
        const uint32_t Bs = As + TILE_B;
        const __half* ga = Ab + (size_t)crow * K + t * 64;
        const __half* gb = Bb + (size_t)crow * K + t * 64;
        const uint32_t arow = As + (uint32_t)crow * 128;
        const uint32_t brow = Bs + (uint32_t)crow * 128;
        const int r7 = crow & 7;
        #pragma unroll
        for (int i = 0; i < 4; i++) {
            const int ch = cbase + i;
            const uint32_t off = (uint32_t)((ch ^ r7) * 16);
            cp16(arow + off, ga + ch * 8);
            cp16(brow + off, gb + ch * 8);
        }
        CP_COMMIT();
    };

    issue(0); issue(1);

    float acc[4][4][4];
    #pragma unroll
    for (int mi = 0; mi < 4; mi++)
        #pragma unroll
        for (int nj = 0; nj < 4; nj++)
            #pragma unroll
            for (int r = 0; r < 4; r++) acc[mi][nj][r] = 0.f;

    // A x4: lanes 0-15 rows 0..15 (chunk lo), lanes 16-31 same rows (chunk hi)
    const int la15 = lane & 15;
    const int lahi = lane >> 4;
    // B x4: lanes 0-7 rows 0-7 lo, 8-15 rows 0-7 hi, 16-23 rows 8-15 lo, 24-31 rows 8-15 hi
    const int lbrow = ((lane >> 4) * 8) + (lane & 7);
    const int lbhi  = (lane >> 3) & 1;

    for (int t = 0; t < nkt; t++) {
        const uint32_t As = sb + (t % 3) * STAGE;
        const uint32_t Bs = As + TILE_B;

        CP_WAIT1();
        __syncthreads();
        if (t + 2 < nkt) issue(t + 2);

        #pragma unroll
        for (int kk = 0; kk < 4; kk++) {         // each kk = K16
            unsigned a[4][4], bq[2][4];
            #pragma unroll
            for (int mi = 0; mi < 4; mi++) {
                const int rowA = wm + mi * 16 + la15;
                const uint32_t addr = As + (uint32_t)rowA * 128
                    + (uint32_t)((((kk * 2) + lahi) ^ (rowA & 7)) * 16);
                ldsm_x4(a[mi], addr);
            }
            #pragma unroll
            for (int p = 0; p < 2; p++) {
                const int rowB = wn + p * 16 + lbrow;
                const uint32_t addr = Bs + (uint32_t)rowB * 128
                    + (uint32_t)((((kk * 2) + lbhi) ^ (rowB & 7)) * 16);
                ldsm_x4(bq[p], addr);
            }
            #pragma unroll
            for (int mi = 0; mi < 4; mi++)
                #pragma unroll
                for (int nj = 0; nj < 4; nj++)
                    mma_f16(acc[mi][nj], a[mi][0], a[mi][1], a[mi][2], a[mi][3],
                            bq[nj >> 1][(nj & 1) * 2], bq[nj >> 1][(nj & 1) * 2 + 1]);
        }
    }
    CP_WAIT0();

    // ---- epilogue ----
    #pragma unroll
    for (int mi = 0; mi < 4; mi++) {
        const int row0 = blockIdx.y * 128 + wm + mi * 16 + gid;
        float rb0 = (biasMode == 2) ? __ldg(bias + row0)     : 0.f;
        float rb1 = (biasMode == 2) ? __ldg(bias + row0 + 8) : 0.f;
        #pragma unroll
        for (int nj = 0; nj < 4; nj++) {
            const int col = blockIdx.x * 128 + wn + nj * 8 + 2 * tig;
            float c0 = acc[mi][nj][0] + rb0, c1 = acc[mi][nj][1] + rb0;
            float c2 = acc[mi][nj][2] + rb1, c3 = acc[mi][nj][3] + rb1;
            const size_t i0 = (size_t)(blockIdx.z * sC) + (size_t)row0 * Ntot + col;
            const size_t i1 = i0 + (size_t)8 * Ntot;
            if (halfOut) {
                __half* Ch = (__half*)Cv;
                *(__half2*)(Ch + i0) = __floats2half2_rn(c0, c1);
                *(__half2*)(Ch + i1) = __floats2half2_rn(c2, c3);
            } else {
                float* Cf = (float*)Cv;
                *(float2*)(Cf + i0) = make_float2(c0, c1);
                *(float2*)(Cf + i1) = make_float2(c2, c3);
            }
        }
    }
}

// ---------------------------------------------------------------------------
// softmax over rows of 512: reads fp32 scores + s2 bias, writes fp16 probs.
// ---------------------------------------------------------------------------
__global__ __launch_bounds__(256) void softmax_rows(
    const float* __restrict__ S, const float* __restrict__ s2,
    __half* __restrict__ P, float scale)
{
    const int row  = blockIdx.x * 8 + (threadIdx.x >> 5);
    const int lane = threadIdx.x & 31;
    const int b    = row >> 10;
    const float4* r4 = (const float4*)(S + (size_t)row * LSEQ) + lane;
    const float4* b4 = (const float4*)(s2 + (size_t)b * LSEQ) + lane;

    float4 v[4];
    #pragma unroll
    for (int i = 0; i < 4; i++) {
        v[i] = r4[32 * i];
        float4 w = __ldg(b4 + 32 * i);
        v[i].x = (v[i].x + w.x) * scale; v[i].y = (v[i].y + w.y) * scale;
        v[i].z = (v[i].z + w.z) * scale; v[i].w = (v[i].w + w.w) * scale;
    }
    float mx = -3.4e38f;
    #pragma unroll
    for (int i = 0; i < 4; i++)
        mx = fmaxf(mx, fmaxf(fmaxf(v[i].x, v[i].y), fmaxf(v[i].z, v[i].w)));
    #pragma unroll
    for (int o = 16; o > 0; o >>= 1)
        mx = fmaxf(mx, __shfl_xor_sync(0xffffffffu, mx, o));
    float sum = 0.f;
    #pragma unroll
    for (int i = 0; i < 4; i++) {
        v[i].x = __expf(v[i].x - mx); v[i].y = __expf(v[i].y - mx);
        v[i].z = __expf(v[i].z - mx); v[i].w = __expf(v[i].w - mx);
        sum += v[i].x + v[i].y + v[i].z + v[i].w;
    }
    #pragma unroll
    for (int o = 16; o > 0; o >>= 1)
        sum += __shfl_xor_sync(0xffffffffu, sum, o);
    const float inv = 1.0f / sum;
    uint2* p8 = (uint2*)(P + (size_t)row * LSEQ) + lane;
    #pragma unroll
    for (int i = 0; i < 4; i++) {
        uint2 u;
        u.x = h2u(__floats2half2_rn(v[i].x * inv, v[i].y * inv));
        u.y = h2u(__floats2half2_rn(v[i].z * inv, v[i].w * inv));
        p8[32 * i] = u;
    }
}

extern "C" void kernel_launch(void* const* d_in, const int* in_sizes, int n_in,
                              void* d_out, int out_size)
{
    const float* q   = (const float*)d_in[0];
    const float* k   = (const float*)d_in[1];
    const float* v   = (const float*)d_in[2];
    const float* q_w = (const float*)d_in[3];
    const float* q_b = (const float*)d_in[4];
    const float* k_w = (const float*)d_in[5];
    const float* v_w = (const float*)d_in[7];
    const float* v_b = (const float*)d_in[8];
    float* out = (float*)d_out;

    __half *rq, *rk, *rv, *rwv, *rwqt, *rwkt, *gt, *qg, *vpt, *p;
    float *w2, *s2p, *s;
    cudaGetSymbolAddress((void**)&rq,   g_rq);
    cudaGetSymbolAddress((void**)&rk,   g_rk);
    cudaGetSymbolAddress((void**)&rv,   g_rv);
    cudaGetSymbolAddress((void**)&rwv,  g_rwv);
    cudaGetSymbolAddress((void**)&rwqt, g_rwqt);
    cudaGetSymbolAddress((void**)&rwkt, g_rwkt);
    cudaGetSymbolAddress((void**)&gt,   g_gt);
    cudaGetSymbolAddress((void**)&w2,   g_w2);
    cudaGetSymbolAddress((void**)&s2p,  g_s2);
    cudaGetSymbolAddress((void**)&qg,   g_qg);
    cudaGetSymbolAddress((void**)&vpt,  g_vpt);
    cudaGetSymbolAddress((void**)&s,    g_s);
    cudaGetSymbolAddress((void**)&p,    g_p);

    static cudaStream_t s1 = nullptr, s2 = nullptr, s3 = nullptr;
    static cudaEvent_t eFork, eRound3, eGt, eS2, eVpt, eQg, eDone;
    if (!s1) {
        cudaStreamCreateWithFlags(&s1, cudaStreamNonBlocking);
        cudaStreamCreateWithFlags(&s2, cudaStreamNonBlocking);
        cudaStreamCreateWithFlags(&s3, cudaStreamNonBlocking);
        cudaEventCreateWithFlags(&eFork,   cudaEventDisableTiming);
        cudaEventCreateWithFlags(&eRound3, cudaEventDisableTiming);
        cudaEventCreateWithFlags(&eGt,     cudaEventDisableTiming);
        cudaEventCreateWithFlags(&eS2,     cudaEventDisableTiming);
        cudaEventCreateWithFlags(&eVpt,    cudaEventDisableTiming);
        cudaEventCreateWithFlags(&eQg,     cudaEventDisableTiming);
        cudaEventCreateWithFlags(&eDone,   cudaEventDisableTiming);
        cudaFuncSetAttribute(hgemm_nt, cudaFuncAttributeMaxDynamicSharedMemorySize, SMEM_BYTES);
    }

    const int nq4 = BATCH * NQ * DIM / 4;
    const int nk4 = BATCH * LSEQ * DIM / 4;
    const float SCALE = 0.03608439182435161f;

    // ---- fork ----
    cudaEventRecord(eFork, 0);
    cudaStreamWaitEvent(s1, eFork, 0);
    cudaStreamWaitEvent(s2, eFork, 0);
    cudaStreamWaitEvent(s3, eFork, 0);

    // s0: round q,k,v -> fp16
    round3_h<<<(nq4 + 2 * nk4) / 256, 256, 0, 0>>>(q, rq, k, rk, v, rv, nq4, nk4);
    cudaEventRecord(eRound3, 0);

    // s1: weight transpose/round -> Gt -> (after round3) vpt
    transpose_round<<<dim3(24, 24, 3), dim3(32, 8), 0, s1>>>(q_w, rwqt, k_w, rwkt, v_w, rwv);
    hgemm_nt<<<dim3(DIM / 128, DIM / 128, 1), 256, SMEM_BYTES, s1>>>(
        rwkt, rwqt, nullptr, gt, DIM, DIM, 0, 0, 0, 0, 1);
    cudaEventRecord(eGt, s1);
    cudaStreamWaitEvent(s1, eRound3, 0);
    hgemm_nt<<<dim3(LSEQ / 128, DIM / 128, BATCH), 256, SMEM_BYTES, s1>>>(
        rwv, rv, v_b, vpt, DIM, LSEQ,
        0, (long)LSEQ * DIM, (long)DIM * LSEQ, 2, 1);
    cudaEventRecord(eVpt, s1);

    // s2: w2 -> (after round3) s2
    compute_w2<<<DIM / 32, 256, 0, s2>>>(k_w, q_b, w2);
    cudaStreamWaitEvent(s2, eRound3, 0);
    compute_s2<<<(BATCH * LSEQ) / 8, 256, 0, s2>>>(rk, w2, s2p);
    cudaEventRecord(eS2, s2);

    // s0: qG = rq @ Gt^T
    cudaStreamWaitEvent(0, eGt, 0);
    hgemm_nt<<<dim3(DIM / 128, (BATCH * NQ) / 128, 1), 256, SMEM_BYTES, 0>>>(
        rq, gt, nullptr, qg, DIM, DIM, 0, 0, 0, 0, 1);
    cudaEventRecord(eQg, 0);
    cudaStreamWaitEvent(s3, eQg, 0);

    // ---- batch halves: s0 -> b 0..15, s3 -> b 16..31 ----
    const size_t oQG  = (size_t)HB * NQ * DIM;
    const size_t oRK  = (size_t)HB * LSEQ * DIM;
    const size_t oS   = (size_t)HB * NQ * LSEQ;
    const size_t oS2  = (size_t)HB * LSEQ;
    const size_t oVPT = (size_t)HB * DIM * LSEQ;
    const size_t oOUT = (size_t)HB * NQ * DIM;

    // S halves (fp32 out)
    hgemm_nt<<<dim3(LSEQ / 128, NQ / 128, HB), 256, SMEM_BYTES, 0>>>(
        qg, rk, nullptr, s, DIM, LSEQ,
        (long)NQ * DIM, (long)LSEQ * DIM, (long)NQ * LSEQ, 0, 0);
    hgemm_nt<<<dim3(LSEQ / 128, NQ / 128, HB), 256, SMEM_BYTES, s3>>>(
        qg + oQG, rk + oRK, nullptr, s + oS, DIM, LSEQ,
        (long)NQ * DIM, (long)LSEQ * DIM, (long)NQ * LSEQ, 0, 0);

    // softmax halves -> fp16 probs
    cudaStreamWaitEvent(0, eS2, 0);
    softmax_rows<<<(HB * NQ) / 8, 256, 0, 0>>>(s, s2p, p, SCALE);
    cudaStreamWaitEvent(s3, eS2, 0);
    softmax_rows<<<(HB * NQ) / 8, 256, 0, s3>>>(s + oS, s2p + oS2, p + oS, SCALE);

    // out halves (fp32 out to d_out)
    cudaStreamWaitEvent(0, eVpt, 0);
    hgemm_nt<<<dim3(DIM / 128, NQ / 128, HB), 256, SMEM_BYTES, 0>>>(
        p, vpt, nullptr, out, LSEQ, DIM,
        (long)NQ * LSEQ, (long)DIM * LSEQ, (long)NQ * DIM, 0, 0);
    cudaStreamWaitEvent(s3, eVpt, 0);
    hgemm_nt<<<dim3(DIM / 128, NQ / 128, HB), 256, SMEM_BYTES, s3>>>(
        p + oS, vpt + oVPT, nullptr, out + oOUT, LSEQ, DIM,
        (long)NQ * LSEQ, (long)DIM * LSEQ, (long)NQ * DIM, 0, 0);

    // ---- join ----
    cudaEventRecord(eDone, s3);
    cudaStreamWaitEvent(0, eDone, 0);
}

// round 11
// speedup vs baseline: 3.0045x; 1.0102x over previous
#include <cuda_runtime.h>
#include <cuda_fp16.h>
#include <cstdint>
#include <cstddef>

#define BATCH 32
#define NQ    1024
#define LSEQ  512
#define DIM   768
#define HB    16   // half-batch

// Scratch (device globals) — GEMM operands fp16
__device__ __half g_rq  [(size_t)BATCH * NQ   * DIM ];
__device__ __half g_rk  [(size_t)BATCH * LSEQ * DIM ];
__device__ __half g_rv  [(size_t)BATCH * LSEQ * DIM ];
__device__ __half g_rwv [DIM * DIM];
__device__ __half g_rwqt[DIM * DIM];
__device__ __half g_rwkt[DIM * DIM];
__device__ __half g_gt  [DIM * DIM];
__device__ float  g_w2  [DIM];
__device__ float  g_s2  [(size_t)BATCH * LSEQ];
__device__ __half g_qg  [(size_t)BATCH * NQ   * DIM ];
__device__ __half g_vpt [(size_t)BATCH * DIM  * LSEQ];
__device__ float  g_s   [(size_t)BATCH * NQ   * LSEQ];   // raw scores (fp32)
__device__ __half g_p   [(size_t)BATCH * NQ   * LSEQ];   // softmax probs (fp16)

__device__ __forceinline__ void mma_f16(float c[4],
    unsigned a0, unsigned a1, unsigned a2, unsigned a3,
    unsigned b0, unsigned b1)
{
    asm("mma.sync.aligned.m16n8k16.row.col.f32.f16.f16.f32 "
        "{%0,%1,%2,%3},{%4,%5,%6,%7},{%8,%9},{%0,%1,%2,%3};"
        : "+f"(c[0]), "+f"(c[1]), "+f"(c[2]), "+f"(c[3])
        : "r"(a0), "r"(a1), "r"(a2), "r"(a3), "r"(b0), "r"(b1));
}

__device__ __forceinline__ void ldsm_x4(unsigned r[4], uint32_t addr) {
    asm volatile("ldmatrix.sync.aligned.m8n8.x4.shared.b16 {%0,%1,%2,%3}, [%4];"
        : "=r"(r[0]), "=r"(r[1]), "=r"(r[2]), "=r"(r[3]) : "r"(addr));
}

__device__ __forceinline__ void cp16(uint32_t dst, const void* src) {
    asm volatile("cp.async.cg.shared.global [%0], [%1], 16;" :: "r"(dst), "l"(src));
}
#define CP_COMMIT() asm volatile("cp.async.commit_group;" ::: "memory")
#define CP_WAIT1()  asm volatile("cp.async.wait_group 1;" ::: "memory")
#define CP_WAIT0()  asm volatile("cp.async.wait_group 0;" ::: "memory")

__device__ __forceinline__ uint32_t s2u(const void* p) {
    uint32_t a;
    asm("{ .reg .u64 t; cvta.to.shared.u64 t, %1; cvt.u32.u64 %0, t; }"
        : "=r"(a) : "l"(p));
    return a;
}

__device__ __forceinline__ unsigned h2u(__half2 h) {
    return *(unsigned*)&h;
}

// ---------------------------------------------------------------------------
// 3-segment fp32 -> fp16 rounding (rn)
// ---------------------------------------------------------------------------
__global__ __launch_bounds__(256) void round3_h(
    const float* __restrict__ s0, __half* __restrict__ d0,
    const float* __restrict__ s1, __half* __restrict__ d1,
    const float* __restrict__ s2, __half* __restrict__ d2,
    int a4, int b4)
{
    int i = blockIdx.x * 256 + threadIdx.x;
    const float* src; __half* dst; int j;
    if (i < a4)            { src = s0; dst = d0; j = i; }
    else if (i < a4 + b4)  { src = s1; dst = d1; j = i - a4; }
    else                   { src = s2; dst = d2; j = i - a4 - b4; }
    float4 v = ((const float4*)src)[j];
    uint2 u;
    u.x = h2u(__floats2half2_rn(v.x, v.y));
    u.y = h2u(__floats2half2_rn(v.z, v.w));
    ((uint2*)dst)[j] = u;
}

// ---------------------------------------------------------------------------
// z=0: q_w -> rwqt transposed+rounded; z=1: k_w -> rwkt; z=2: v_w -> rwv copy.
// ---------------------------------------------------------------------------
__global__ __launch_bounds__(256) void transpose_round(
    const float* __restrict__ qw, __half* __restrict__ dqt,
    const float* __restrict__ kw, __half* __restrict__ dkt,
    const float* __restrict__ vw, __half* __restrict__ dv)
{
    const int tx = threadIdx.x, ty = threadIdx.y;
    const int x = blockIdx.x * 32 + tx;
    const int y = blockIdx.y * 32 + ty;

    if (blockIdx.z == 2) {
        #pragma unroll
        for (int i = 0; i < 32; i += 8)
            dv[(size_t)(y + i) * DIM + x] = __float2half_rn(vw[(size_t)(y + i) * DIM + x]);
        return;
    }

    __shared__ float tile[32][33];
    const float* src = blockIdx.z ? kw : qw;
    __half*      dst = blockIdx.z ? dkt : dqt;
    #pragma unroll
    for (int i = 0; i < 32; i += 8)
        tile[ty + i][tx] = src[(size_t)(y + i) * DIM + x];
    __syncthreads();
    const int xo = blockIdx.y * 32 + tx;
    const int yo = blockIdx.x * 32 + ty;
    #pragma unroll
    for (int i = 0; i < 32; i += 8)
        dst[(size_t)(yo + i) * DIM + xo] = __float2half_rn(tile[tx][ty + i]);
}

// ---------------------------------------------------------------------------
__global__ __launch_bounds__(256) void compute_w2(
    const float* __restrict__ kw, const float* __restrict__ bq,
    float* __restrict__ w2)
{
    __shared__ float part[8][32];
    const int cl = threadIdx.x & 31;
    const int dg = threadIdx.x >> 5;
    const int c  = blockIdx.x * 32 + cl;
    float acc = 0.f;
    const int d0 = dg * 96;
    #pragma unroll 8
    for (int d = d0; d < d0 + 96; d++)
        acc += __ldg(bq + d) * __ldg(kw + (size_t)d * DIM + c);
    part[dg][cl] = acc;
    __syncthreads();
    if (dg == 0) {
        float s = 0.f;
        #pragma unroll
        for (int i = 0; i < 8; i++) s += part[i][cl];
        w2[c] = s;
    }
}

// ---------------------------------------------------------------------------
// s2[row] = rk[row,:] . w2   (rk fp16, w2 fp32), one warp per row
// ---------------------------------------------------------------------------
__global__ __launch_bounds__(256) void compute_s2(
    const __half* __restrict__ rk, const float* __restrict__ w2,
    float* __restrict__ s2)
{
    const int row  = blockIdx.x * 8 + (threadIdx.x >> 5);
    const int lane = threadIdx.x & 31;
    const uint4*  kr = (const uint4*)(rk + (size_t)row * DIM);
    const float4* w4 = (const float4*)w2;
    float acc = 0.f;
    #pragma unroll
    for (int i = 0; i < 3; i++) {
        const int c = lane + 32 * i;
        uint4 u = kr[c];
        float4 wa = __ldg(w4 + 2 * c), wb = __ldg(w4 + 2 * c + 1);
        float2 f;
        f = __half22float2(*(__half2*)&u.x); acc += f.x * wa.x + f.y * wa.y;
        f = __half22float2(*(__half2*)&u.y); acc += f.x * wa.z + f.y * wa.w;
        f = __half22float2(*(__half2*)&u.z); acc += f.x * wb.x + f.y * wb.y;
        f = __half22float2(*(__half2*)&u.w); acc += f.x * wb.z + f.y * wb.w;
    }
    #pragma unroll
    for (int o = 16; o > 0; o >>= 1)
        acc += __shfl_xor_sync(0xffffffffu, acc, o);
    if (lane == 0) s2[row] = acc;
}

// ---------------------------------------------------------------------------
// C[M,N] = A[M,K] @ B[N,K]^T (+bias). fp16 in, fp32 accum. UNCHANGED (proven).
// ---------------------------------------------------------------------------
#define TILE_B  16384
#define STAGE   (2 * TILE_B)
#define SMEM_BYTES (3 * STAGE)

__global__ __launch_bounds__(256, 2) void hgemm_nt(
    const __half* __restrict__ A, const __half* __restrict__ Bm,
    const float* __restrict__ bias, void* __restrict__ Cv,
    int K, int Ntot, long sA, long sB, long sC, int biasMode, int halfOut)
{
    extern __shared__ char smem[];
    const uint32_t sb = s2u(smem);

    const int tid  = threadIdx.x;
    const int lane = tid & 31;
    const int wid  = tid >> 5;
    const int wm   = (wid >> 2) * 64;
    const int wn   = (wid & 3) * 32;
    const int gid  = lane >> 2;
    const int tig  = lane & 3;

    const __half* Ab = A  + (size_t)blockIdx.z * sA + (size_t)blockIdx.y * 128 * K;
    const __half* Bb = Bm + (size_t)blockIdx.z * sB + (size_t)blockIdx.x * 128 * K;

    const int crow  = tid >> 1;
    const int cbase = (tid & 1) * 4;
    const int nkt   = K / 64;

    auto issue = [&](int t) {
        const int s = t % 3;
        const uint32_t As = sb + s * STAGE;
        const uint32_t Bs = As + TILE_B;
        const __half* ga = Ab + (size_t)crow * K + t * 64;
        const __half* gb = Bb + (size_t)crow * K + t * 64;
        const uint32_t arow = As + (uint32_t)crow * 128;
        const uint32_t brow = Bs + (uint32_t)crow * 128;
        const int r7 = crow & 7;
        #pragma unroll
        for (int i = 0; i < 4; i++) {
            const int ch = cbase + i;
            const uint32_t off = (uint32_t)((ch ^ r7) * 16);
            cp16(arow + off, ga + ch * 8);
            cp16(brow + off, gb + ch * 8);
        }
        CP_COMMIT();
    };

    issue(0); issue(1);

    float acc[4][4][4];
    #pragma unroll
    for (int mi = 0; mi < 4; mi++)
        #pragma unroll
        for (int nj = 0; nj < 4; nj++)
            #pragma unroll
            for (int r = 0; r < 4; r++) acc[mi][nj][r] = 0.f;

    const int la15 = lane & 15;
    const int lahi = lane >> 4;
    const int lbrow = ((lane >> 4) * 8) + (lane & 7);
    const int lbhi  = (lane >> 3) & 1;

    for (int t = 0; t < nkt; t++) {
        const uint32_t As = sb + (t % 3) * STAGE;
        const uint32_t Bs = As + TILE_B;

        CP_WAIT1();
        __syncthreads();
        if (t + 2 < nkt) issue(t + 2);

        #pragma unroll
        for (int kk = 0; kk < 4; kk++) {
            unsigned a[4][4], bq[2][4];
            #pragma unroll
            for (int mi = 0; mi < 4; mi++) {
                const int rowA = wm + mi * 16 + la15;
                const uint32_t addr = As + (uint32_t)rowA * 128
                    + (uint32_t)((((kk * 2) + lahi) ^ (rowA & 7)) * 16);
                ldsm_x4(a[mi], addr);
            }
            #pragma unroll
            for (int p = 0; p < 2; p++) {
                const int rowB = wn + p * 16 + lbrow;
                const uint32_t addr = Bs + (uint32_t)rowB * 128
                    + (uint32_t)((((kk * 2) + lbhi) ^ (rowB & 7)) * 16);
                ldsm_x4(bq[p], addr);
            }
            #pragma unroll
            for (int mi = 0; mi < 4; mi++)
                #pragma unroll
                for (int nj = 0; nj < 4; nj++)
                    mma_f16(acc[mi][nj], a[mi][0], a[mi][1], a[mi][2], a[mi][3],
                            bq[nj >> 1][(nj & 1) * 2], bq[nj >> 1][(nj & 1) * 2 + 1]);
        }
    }
    CP_WAIT0();

    #pragma unroll
    for (int mi = 0; mi < 4; mi++) {
        const int row0 = blockIdx.y * 128 + wm + mi * 16 + gid;
        float rb0 = (biasMode == 2) ? __ldg(bias + row0)     : 0.f;
        float rb1 = (biasMode == 2) ? __ldg(bias + row0 + 8) : 0.f;
        #pragma unroll
        for (int nj = 0; nj < 4; nj++) {
            const int col = blockIdx.x * 128 + wn + nj * 8 + 2 * tig;
            float c0 = acc[mi][nj][0] + rb0, c1 = acc[mi][nj][1] + rb0;
            float c2 = acc[mi][nj][2] + rb1, c3 = acc[mi][nj][3] + rb1;
            const size_t i0 = (size_t)(blockIdx.z * sC) + (size_t)row0 * Ntot + col;
            const size_t i1 = i0 + (size_t)8 * Ntot;
            if (halfOut) {
                __half* Ch = (__half*)Cv;
                *(__half2*)(Ch + i0) = __floats2half2_rn(c0, c1);
                *(__half2*)(Ch + i1) = __floats2half2_rn(c2, c3);
            } else {
                float* Cf = (float*)Cv;
                *(float2*)(Cf + i0) = make_float2(c0, c1);
                *(float2*)(Cf + i1) = make_float2(c2, c3);
            }
        }
    }
}

// ---------------------------------------------------------------------------
// softmax over rows of 512: fp32 scores + s2 bias -> fp16 probs.
// ---------------------------------------------------------------------------
__global__ __launch_bounds__(256) void softmax_rows(
    const float* __restrict__ S, const float* __restrict__ s2,
    __half* __restrict__ P, float scale)
{
    const int row  = blockIdx.x * 8 + (threadIdx.x >> 5);
    const int lane = threadIdx.x & 31;
    const int b    = row >> 10;
    const float4* r4 = (const float4*)(S + (size_t)row * LSEQ) + lane;
    const float4* b4 = (const float4*)(s2 + (size_t)b * LSEQ) + lane;

    float4 v[4];
    #pragma unroll
    for (int i = 0; i < 4; i++) {
        v[i] = r4[32 * i];
        float4 w = __ldg(b4 + 32 * i);
        v[i].x = (v[i].x + w.x) * scale; v[i].y = (v[i].y + w.y) * scale;
        v[i].z = (v[i].z + w.z) * scale; v[i].w = (v[i].w + w.w) * scale;
    }
    float mx = -3.4e38f;
    #pragma unroll
    for (int i = 0; i < 4; i++)
        mx = fmaxf(mx, fmaxf(fmaxf(v[i].x, v[i].y), fmaxf(v[i].z, v[i].w)));
    #pragma unroll
    for (int o = 16; o > 0; o >>= 1)
        mx = fmaxf(mx, __shfl_xor_sync(0xffffffffu, mx, o));
    float sum = 0.f;
    #pragma unroll
    for (int i = 0; i < 4; i++) {
        v[i].x = __expf(v[i].x - mx); v[i].y = __expf(v[i].y - mx);
        v[i].z = __expf(v[i].z - mx); v[i].w = __expf(v[i].w - mx);
        sum += v[i].x + v[i].y + v[i].z + v[i].w;
    }
    #pragma unroll
    for (int o = 16; o > 0; o >>= 1)
        sum += __shfl_xor_sync(0xffffffffu, sum, o);
    const float inv = 1.0f / sum;
    uint2* p8 = (uint2*)(P + (size_t)row * LSEQ) + lane;
    #pragma unroll
    for (int i = 0; i < 4; i++) {
        uint2 u;
        u.x = h2u(__floats2half2_rn(v[i].x * inv, v[i].y * inv));
        u.y = h2u(__floats2half2_rn(v[i].z * inv, v[i].w * inv));
        p8[32 * i] = u;
    }
}

extern "C" void kernel_launch(void* const* d_in, const int* in_sizes, int n_in,
                              void* d_out, int out_size)
{
    const float* q   = (const float*)d_in[0];
    const float* k   = (const float*)d_in[1];
    const float* v   = (const float*)d_in[2];
    const float* q_w = (const float*)d_in[3];
    const float* q_b = (const float*)d_in[4];
    const float* k_w = (const float*)d_in[5];
    const float* v_w = (const float*)d_in[7];
    const float* v_b = (const float*)d_in[8];
    float* out = (float*)d_out;

    __half *rq, *rk, *rv, *rwv, *rwqt, *rwkt, *gt, *qg, *vpt, *p;
    float *w2, *s2p, *s;
    cudaGetSymbolAddress((void**)&rq,   g_rq);
    cudaGetSymbolAddress((void**)&rk,   g_rk);
    cudaGetSymbolAddress((void**)&rv,   g_rv);
    cudaGetSymbolAddress((void**)&rwv,  g_rwv);
    cudaGetSymbolAddress((void**)&rwqt, g_rwqt);
    cudaGetSymbolAddress((void**)&rwkt, g_rwkt);
    cudaGetSymbolAddress((void**)&gt,   g_gt);
    cudaGetSymbolAddress((void**)&w2,   g_w2);
    cudaGetSymbolAddress((void**)&s2p,  g_s2);
    cudaGetSymbolAddress((void**)&qg,   g_qg);
    cudaGetSymbolAddress((void**)&vpt,  g_vpt);
    cudaGetSymbolAddress((void**)&s,    g_s);
    cudaGetSymbolAddress((void**)&p,    g_p);

    static cudaStream_t s1 = nullptr, s2 = nullptr, s3 = nullptr;
    static cudaEvent_t eFork, eRq, eRkv, eGt, eS2, eVpt, eDone;
    if (!s1) {
        cudaStreamCreateWithFlags(&s1, cudaStreamNonBlocking);
        cudaStreamCreateWithFlags(&s2, cudaStreamNonBlocking);
        cudaStreamCreateWithFlags(&s3, cudaStreamNonBlocking);
        cudaEventCreateWithFlags(&eFork, cudaEventDisableTiming);
        cudaEventCreateWithFlags(&eRq,   cudaEventDisableTiming);
        cudaEventCreateWithFlags(&eRkv,  cudaEventDisableTiming);
        cudaEventCreateWithFlags(&eGt,   cudaEventDisableTiming);
        cudaEventCreateWithFlags(&eS2,   cudaEventDisableTiming);
        cudaEventCreateWithFlags(&eVpt,  cudaEventDisableTiming);
        cudaEventCreateWithFlags(&eDone, cudaEventDisableTiming);
        cudaFuncSetAttribute(hgemm_nt, cudaFuncAttributeMaxDynamicSharedMemorySize, SMEM_BYTES);
    }

    const int nq4 = BATCH * NQ * DIM / 4;
    const int nk4 = BATCH * LSEQ * DIM / 4;
    const float SCALE = 0.03608439182435161f;

    const size_t oQG  = (size_t)HB * NQ * DIM;
    const size_t oRK  = (size_t)HB * LSEQ * DIM;
    const size_t oS   = (size_t)HB * NQ * LSEQ;
    const size_t oS2  = (size_t)HB * LSEQ;
    const size_t oVPT = (size_t)HB * DIM * LSEQ;
    const size_t oOUT = (size_t)HB * NQ * DIM;

    // ---- fork ----
    cudaEventRecord(eFork, 0);
    cudaStreamWaitEvent(s1, eFork, 0);
    cudaStreamWaitEvent(s2, eFork, 0);
    cudaStreamWaitEvent(s3, eFork, 0);

    // s0: round q only (critical path for qG)
    round3_h<<<nq4 / 256, 256, 0, 0>>>(q, rq, q, rq, q, rq, nq4, 0);
    cudaEventRecord(eRq, 0);

    // s1: weight transpose/round -> Gt -> (after round_kv) vpt
    transpose_round<<<dim3(24, 24, 3), dim3(32, 8), 0, s1>>>(q_w, rwqt, k_w, rwkt, v_w, rwv);
    hgemm_nt<<<dim3(DIM / 128, DIM / 128, 1), 256, SMEM_BYTES, s1>>>(
        rwkt, rwqt, nullptr, gt, DIM, DIM, 0, 0, 0, 0, 1);
    cudaEventRecord(eGt, s1);

    // s2: w2 (no deps) -> round k,v -> s2
    compute_w2<<<DIM / 32, 256, 0, s2>>>(k_w, q_b, w2);
    round3_h<<<2 * nk4 / 256, 256, 0, s2>>>(k, rk, v, rv, v, rv, nk4, nk4);
    cudaEventRecord(eRkv, s2);
    compute_s2<<<(BATCH * LSEQ) / 8, 256, 0, s2>>>(rk, w2, s2p);
    cudaEventRecord(eS2, s2);

    // s1: vpt (needs rv)
    cudaStreamWaitEvent(s1, eRkv, 0);
    hgemm_nt<<<dim3(LSEQ / 128, DIM / 128, BATCH), 256, SMEM_BYTES, s1>>>(
        rwv, rv, v_b, vpt, DIM, LSEQ,
        0, (long)LSEQ * DIM, (long)DIM * LSEQ, 2, 1);
    cudaEventRecord(eVpt, s1);

    // s0: qG half 0 (needs Gt + rq)
    cudaStreamWaitEvent(0, eGt, 0);
    hgemm_nt<<<dim3(DIM / 128, (HB * NQ) / 128, 1), 256, SMEM_BYTES, 0>>>(
        rq, gt, nullptr, qg, DIM, DIM, 0, 0, 0, 0, 1);

    // s3: qG half 1 (needs Gt + rq)
    cudaStreamWaitEvent(s3, eGt, 0);
    cudaStreamWaitEvent(s3, eRq, 0);
    hgemm_nt<<<dim3(DIM / 128, (HB * NQ) / 128, 1), 256, SMEM_BYTES, s3>>>(
        rq + oQG, gt, nullptr, qg + oQG, DIM, DIM, 0, 0, 0, 0, 1);

    // S halves (need qG half + rk)
    cudaStreamWaitEvent(0, eRkv, 0);
    hgemm_nt<<<dim3(LSEQ / 128, NQ / 128, HB), 256, SMEM_BYTES, 0>>>(
        qg, rk, nullptr, s, DIM, LSEQ,
        (long)NQ * DIM, (long)LSEQ * DIM, (long)NQ * LSEQ, 0, 0);
    cudaStreamWaitEvent(s3, eRkv, 0);
    hgemm_nt<<<dim3(LSEQ / 128, NQ / 128, HB), 256, SMEM_BYTES, s3>>>(
        qg + oQG, rk + oRK, nullptr, s + oS, DIM, LSEQ,
        (long)NQ * DIM, (long)LSEQ * DIM, (long)NQ * LSEQ, 0, 0);

    // softmax halves -> fp16 probs
    cudaStreamWaitEvent(0, eS2, 0);
    softmax_rows<<<(HB * NQ) / 8, 256, 0, 0>>>(s, s2p, p, SCALE);
    cudaStreamWaitEvent(s3, eS2, 0);
    softmax_rows<<<(HB * NQ) / 8, 256, 0, s3>>>(s + oS, s2p + oS2, p + oS, SCALE);

    // out halves (need vpt)
    cudaStreamWaitEvent(0, eVpt, 0);
    hgemm_nt<<<dim3(DIM / 128, NQ / 128, HB), 256, SMEM_BYTES, 0>>>(
        p, vpt, nullptr, out, LSEQ, DIM,
        (long)NQ * LSEQ, (long)DIM * LSEQ, (long)NQ * DIM, 0, 0);
    cudaStreamWaitEvent(s3, eVpt, 0);
    hgemm_nt<<<dim3(DIM / 128, NQ / 128, HB), 256, SMEM_BYTES, s3>>>(
        p + oS, vpt + oVPT, nullptr, out + oOUT, LSEQ, DIM,
        (long)NQ * LSEQ, (long)DIM * LSEQ, (long)NQ * DIM, 0, 0);

    // ---- join ----
    cudaEventRecord(eDone, s3);
    cudaStreamWaitEvent(0, eDone, 0);
}

// round 12
// speedup vs baseline: 3.4812x; 1.1587x over previous
#include <cuda_runtime.h>
#include <cuda_fp16.h>
#include <cstdint>
#include <cstddef>

#define BATCH 32
#define NQ    1024
#define LSEQ  512
#define DIM   768
#define HB    16   // half-batch

// Scratch (device globals) — GEMM operands fp16
__device__ __half g_rq  [(size_t)BATCH * NQ   * DIM ];
__device__ __half g_rk  [(size_t)BATCH * LSEQ * DIM ];
__device__ __half g_rv  [(size_t)BATCH * LSEQ * DIM ];
__device__ __half g_rwv [DIM * DIM];
__device__ __half g_rwqt[DIM * DIM];
__device__ __half g_rwkt[DIM * DIM];
__device__ __half g_gt2 [DIM * DIM];                     // gt2[c][c'] = sum_d qw[d,c]kw[d,c']
__device__ float  g_w2  [DIM];
__device__ float  g_s2  [(size_t)BATCH * LSEQ];
__device__ __half g_kg  [(size_t)BATCH * LSEQ * DIM ];   // kG[b][l][c]
__device__ __half g_vpt [(size_t)BATCH * DIM  * LSEQ];   // vpT[b][d][l]
__device__ float  g_s   [(size_t)BATCH * NQ   * LSEQ];   // raw scores (fp32)
__device__ __half g_p   [(size_t)BATCH * NQ   * LSEQ];   // softmax probs (fp16)

__device__ __forceinline__ void mma_f16(float c[4],
    unsigned a0, unsigned a1, unsigned a2, unsigned a3,
    unsigned b0, unsigned b1)
{
    asm("mma.sync.aligned.m16n8k16.row.col.f32.f16.f16.f32 "
        "{%0,%1,%2,%3},{%4,%5,%6,%7},{%8,%9},{%0,%1,%2,%3};"
        : "+f"(c[0]), "+f"(c[1]), "+f"(c[2]), "+f"(c[3])
        : "r"(a0), "r"(a1), "r"(a2), "r"(a3), "r"(b0), "r"(b1));
}

__device__ __forceinline__ void ldsm_x4(unsigned r[4], uint32_t addr) {
    asm volatile("ldmatrix.sync.aligned.m8n8.x4.shared.b16 {%0,%1,%2,%3}, [%4];"
        : "=r"(r[0]), "=r"(r[1]), "=r"(r[2]), "=r"(r[3]) : "r"(addr));
}

__device__ __forceinline__ void cp16(uint32_t dst, const void* src) {
    asm volatile("cp.async.cg.shared.global [%0], [%1], 16;" :: "r"(dst), "l"(src));
}
#define CP_COMMIT() asm volatile("cp.async.commit_group;" ::: "memory")
#define CP_WAIT1()  asm volatile("cp.async.wait_group 1;" ::: "memory")
#define CP_WAIT0()  asm volatile("cp.async.wait_group 0;" ::: "memory")

__device__ __forceinline__ uint32_t s2u(const void* p) {
    uint32_t a;
    asm("{ .reg .u64 t; cvta.to.shared.u64 t, %1; cvt.u32.u64 %0, t; }"
        : "=r"(a) : "l"(p));
    return a;
}

__device__ __forceinline__ unsigned h2u(__half2 h) {
    return *(unsigned*)&h;
}

// ---------------------------------------------------------------------------
// 3-segment fp32 -> fp16 rounding (rn)
// ---------------------------------------------------------------------------
__global__ __launch_bounds__(256) void round3_h(
    const float* __restrict__ s0, __half* __restrict__ d0,
    const float* __restrict__ s1, __half* __restrict__ d1,
    const float* __restrict__ s2, __half* __restrict__ d2,
    int a4, int b4)
{
    int i = blockIdx.x * 256 + threadIdx.x;
    const float* src; __half* dst; int j;
    if (i < a4)            { src = s0; dst = d0; j = i; }
    else if (i < a4 + b4)  { src = s1; dst = d1; j = i - a4; }
    else                   { src = s2; dst = d2; j = i - a4 - b4; }
    float4 v = ((const float4*)src)[j];
    uint2 u;
    u.x = h2u(__floats2half2_rn(v.x, v.y));
    u.y = h2u(__floats2half2_rn(v.z, v.w));
    ((uint2*)dst)[j] = u;
}

// ---------------------------------------------------------------------------
// z=0: q_w -> rwqt transposed+rounded; z=1: k_w -> rwkt; z=2: v_w -> rwv copy.
// ---------------------------------------------------------------------------
__global__ __launch_bounds__(256) void transpose_round(
    const float* __restrict__ qw, __half* __restrict__ dqt,
    const float* __restrict__ kw, __half* __restrict__ dkt,
    const float* __restrict__ vw, __half* __restrict__ dv)
{
    const int tx = threadIdx.x, ty = threadIdx.y;
    const int x = blockIdx.x * 32 + tx;
    const int y = blockIdx.y * 32 + ty;

    if (blockIdx.z == 2) {
        #pragma unroll
        for (int i = 0; i < 32; i += 8)
            dv[(size_t)(y + i) * DIM + x] = __float2half_rn(vw[(size_t)(y + i) * DIM + x]);
        return;
    }

    __shared__ float tile[32][33];
    const float* src = blockIdx.z ? kw : qw;
    __half*      dst = blockIdx.z ? dkt : dqt;
    #pragma unroll
    for (int i = 0; i < 32; i += 8)
        tile[ty + i][tx] = src[(size_t)(y + i) * DIM + x];
    __syncthreads();
    const int xo = blockIdx.y * 32 + tx;
    const int yo = blockIdx.x * 32 + ty;
    #pragma unroll
    for (int i = 0; i < 32; i += 8)
        dst[(size_t)(yo + i) * DIM + xo] = __float2half_rn(tile[tx][ty + i]);
}

// ---------------------------------------------------------------------------
__global__ __launch_bounds__(256) void compute_w2(
    const float* __restrict__ kw, const float* __restrict__ bq,
    float* __restrict__ w2)
{
    __shared__ float part[8][32];
    const int cl = threadIdx.x & 31;
    const int dg = threadIdx.x >> 5;
    const int c  = blockIdx.x * 32 + cl;
    float acc = 0.f;
    const int d0 = dg * 96;
    #pragma unroll 8
    for (int d = d0; d < d0 + 96; d++)
        acc += __ldg(bq + d) * __ldg(kw + (size_t)d * DIM + c);
    part[dg][cl] = acc;
    __syncthreads();
    if (dg == 0) {
        float s = 0.f;
        #pragma unroll
        for (int i = 0; i < 8; i++) s += part[i][cl];
        w2[c] = s;
    }
}

// ---------------------------------------------------------------------------
// s2[row] = rk[row,:] . w2   (rk fp16, w2 fp32), one warp per row
// ---------------------------------------------------------------------------
__global__ __launch_bounds__(256) void compute_s2(
    const __half* __restrict__ rk, const float* __restrict__ w2,
    float* __restrict__ s2)
{
    const int row  = blockIdx.x * 8 + (threadIdx.x >> 5);
    const int lane = threadIdx.x & 31;
    const uint4*  kr = (const uint4*)(rk + (size_t)row * DIM);
    const float4* w4 = (const float4*)w2;
    float acc = 0.f;
    #pragma unroll
    for (int i = 0; i < 3; i++) {
        const int c = lane + 32 * i;
        uint4 u = kr[c];
        float4 wa = __ldg(w4 + 2 * c), wb = __ldg(w4 + 2 * c + 1);
        float2 f;
        f = __half22float2(*(__half2*)&u.x); acc += f.x * wa.x + f.y * wa.y;
        f = __half22float2(*(__half2*)&u.y); acc += f.x * wa.z + f.y * wa.w;
        f = __half22float2(*(__half2*)&u.z); acc += f.x * wb.x + f.y * wb.y;
        f = __half22float2(*(__half2*)&u.w); acc += f.x * wb.z + f.y * wb.w;
    }
    #pragma unroll
    for (int o = 16; o > 0; o >>= 1)
        acc += __shfl_xor_sync(0xffffffffu, acc, o);
    if (lane == 0) s2[row] = acc;
}

// ---------------------------------------------------------------------------
// C[M,N] = A[M,K] @ B[N,K]^T (+bias). fp16 in, fp32 accum. UNCHANGED (proven).
// ---------------------------------------------------------------------------
#define TILE_B  16384
#define STAGE   (2 * TILE_B)
#define SMEM_BYTES (3 * STAGE)

__global__ __launch_bounds__(256, 2) void hgemm_nt(
    const __half* __restrict__ A, const __half* __restrict__ Bm,
    const float* __restrict__ bias, void* __restrict__ Cv,
    int K, int Ntot, long sA, long sB, long sC, int biasMode, int halfOut)
{
    extern __shared__ char smem[];
    const uint32_t sb = s2u(smem);

    const int tid  = threadIdx.x;
    const int lane = tid & 31;
    const int wid  = tid >> 5;
    const int wm   = (wid >> 2) * 64;
    const int wn   = (wid & 3) * 32;
    const int gid  = lane >> 2;
    const int tig  = lane & 3;

    const __half* Ab = A  + (size_t)blockIdx.z * sA + (size_t)blockIdx.y * 128 * K;
    const __half* Bb = Bm + (size_t)blockIdx.z * sB + (size_t)blockIdx.x * 128 * K;

    const int crow  = tid >> 1;
    const int cbase = (tid & 1) * 4;
    const int nkt   = K / 64;

    auto issue = [&](int t) {
        const int s = t % 3;
        const uint32_t As = sb + s * STAGE;
        const uint32_t Bs = As + TILE_B;
        const __half* ga = Ab + (size_t)crow * K + t * 64;
        const __half* gb = Bb + (size_t)crow * K + t * 64;
        const uint32_t arow = As + (uint32_t)crow * 128;
        const uint32_t brow = Bs + (uint32_t)crow * 128;
        const int r7 = crow & 7;
        #pragma unroll
        for (int i = 0; i < 4; i++) {
            const int ch = cbase + i;
            const uint32_t off = (uint32_t)((ch ^ r7) * 16);
            cp16(arow + off, ga + ch * 8);
            cp16(brow + off, gb + ch * 8);
        }
        CP_COMMIT();
    };

    issue(0); issue(1);

    float acc[4][4][4];
    #pragma unroll
    for (int mi = 0; mi < 4; mi++)
        #pragma unroll
        for (int nj = 0; nj < 4; nj++)
            #pragma unroll
            for (int r = 0; r < 4; r++) acc[mi][nj][r] = 0.f;

    const int la15 = lane & 15;
    const int lahi = lane >> 4;
    const int lbrow = ((lane >> 4) * 8) + (lane & 7);
    const int lbhi  = (lane >> 3) & 1;

    for (int t = 0; t < nkt; t++) {
        const uint32_t As = sb + (t % 3) * STAGE;
        const uint32_t Bs = As + TILE_B;

        CP_WAIT1();
        __syncthreads();
        if (t + 2 < nkt) issue(t + 2);

        #pragma unroll
        for (int kk = 0; kk < 4; kk++) {
            unsigned a[4][4], bq[2][4];
            #pragma unroll
            for (int mi = 0; mi < 4; mi++) {
                const int rowA = wm + mi * 16 + la15;
                const uint32_t addr = As + (uint32_t)rowA * 128
                    + (uint32_t)((((kk * 2) + lahi) ^ (rowA & 7)) * 16);
                ldsm_x4(a[mi], addr);
            }
            #pragma unroll
            for (int p = 0; p < 2; p++) {
                const int rowB = wn + p * 16 + lbrow;
                const uint32_t addr = Bs + (uint32_t)rowB * 128
                    + (uint32_t)((((kk * 2) + lbhi) ^ (rowB & 7)) * 16);
                ldsm_x4(bq[p], addr);
            }
            #pragma unroll
            for (int mi = 0; mi < 4; mi++)
                #pragma unroll
                for (int nj = 0; nj < 4; nj++)
                    mma_f16(acc[mi][nj], a[mi][0], a[mi][1], a[mi][2], a[mi][3],
                            bq[nj >> 1][(nj & 1) * 2], bq[nj >> 1][(nj & 1) * 2 + 1]);
        }
    }
    CP_WAIT0();

    #pragma unroll
    for (int mi = 0; mi < 4; mi++) {
        const int row0 = blockIdx.y * 128 + wm + mi * 16 + gid;
        float rb0 = (biasMode == 2) ? __ldg(bias + row0)     : 0.f;
        float rb1 = (biasMode == 2) ? __ldg(bias + row0 + 8) : 0.f;
        #pragma unroll
        for (int nj = 0; nj < 4; nj++) {
            const int col = blockIdx.x * 128 + wn + nj * 8 + 2 * tig;
            float c0 = acc[mi][nj][0] + rb0, c1 = acc[mi][nj][1] + rb0;
            float c2 = acc[mi][nj][2] + rb1, c3 = acc[mi][nj][3] + rb1;
            const size_t i0 = (size_t)(blockIdx.z * sC) + (size_t)row0 * Ntot + col;
            const size_t i1 = i0 + (size_t)8 * Ntot;
            if (halfOut) {
                __half* Ch = (__half*)Cv;
                *(__half2*)(Ch + i0) = __floats2half2_rn(c0, c1);
                *(__half2*)(Ch + i1) = __floats2half2_rn(c2, c3);
            } else {
                float* Cf = (float*)Cv;
                *(float2*)(Cf + i0) = make_float2(c0, c1);
                *(float2*)(Cf + i1) = make_float2(c2, c3);
            }
        }
    }
}

// ---------------------------------------------------------------------------
// softmax over rows of 512: fp32 scores + s2 bias -> fp16 probs.
// ---------------------------------------------------------------------------
__global__ __launch_bounds__(256) void softmax_rows(
    const float* __restrict__ S, const float* __restrict__ s2,
    __half* __restrict__ P, float scale)
{
    const int row  = blockIdx.x * 8 + (threadIdx.x >> 5);
    const int lane = threadIdx.x & 31;
    const int b    = row >> 10;
    const float4* r4 = (const float4*)(S + (size_t)row * LSEQ) + lane;
    const float4* b4 = (const float4*)(s2 + (size_t)b * LSEQ) + lane;

    float4 v[4];
    #pragma unroll
    for (int i = 0; i < 4; i++) {
        v[i] = r4[32 * i];
        float4 w = __ldg(b4 + 32 * i);
        v[i].x = (v[i].x + w.x) * scale; v[i].y = (v[i].y + w.y) * scale;
        v[i].z = (v[i].z + w.z) * scale; v[i].w = (v[i].w + w.w) * scale;
    }
    float mx = -3.4e38f;
    #pragma unroll
    for (int i = 0; i < 4; i++)
        mx = fmaxf(mx, fmaxf(fmaxf(v[i].x, v[i].y), fmaxf(v[i].z, v[i].w)));
    #pragma unroll
    for (int o = 16; o > 0; o >>= 1)
        mx = fmaxf(mx, __shfl_xor_sync(0xffffffffu, mx, o));
    float sum = 0.f;
    #pragma unroll
    for (int i = 0; i < 4; i++) {
        v[i].x = __expf(v[i].x - mx); v[i].y = __expf(v[i].y - mx);
        v[i].z = __expf(v[i].z - mx); v[i].w = __expf(v[i].w - mx);
        sum += v[i].x + v[i].y + v[i].z + v[i].w;
    }
    #pragma unroll
    for (int o = 16; o > 0; o >>= 1)
        sum += __shfl_xor_sync(0xffffffffu, sum, o);
    const float inv = 1.0f / sum;
    uint2* p8 = (uint2*)(P + (size_t)row * LSEQ) + lane;
    #pragma unroll
    for (int i = 0; i < 4; i++) {
        uint2 u;
        u.x = h2u(__floats2half2_rn(v[i].x * inv, v[i].y * inv));
        u.y = h2u(__floats2half2_rn(v[i].z * inv, v[i].w * inv));
        p8[32 * i] = u;
    }
}

extern "C" void kernel_launch(void* const* d_in, const int* in_sizes, int n_in,
                              void* d_out, int out_size)
{
    const float* q   = (const float*)d_in[0];
    const float* k   = (const float*)d_in[1];
    const float* v   = (const float*)d_in[2];
    const float* q_w = (const float*)d_in[3];
    const float* q_b = (const float*)d_in[4];
    const float* k_w = (const float*)d_in[5];
    const float* v_w = (const float*)d_in[7];
    const float* v_b = (const float*)d_in[8];
    float* out = (float*)d_out;

    __half *rq, *rk, *rv, *rwv, *rwqt, *rwkt, *gt2, *kg, *vpt, *p;
    float *w2, *s2p, *s;
    cudaGetSymbolAddress((void**)&rq,   g_rq);
    cudaGetSymbolAddress((void**)&rk,   g_rk);
    cudaGetSymbolAddress((void**)&rv,   g_rv);
    cudaGetSymbolAddress((void**)&rwv,  g_rwv);
    cudaGetSymbolAddress((void**)&rwqt, g_rwqt);
    cudaGetSymbolAddress((void**)&rwkt, g_rwkt);
    cudaGetSymbolAddress((void**)&gt2,  g_gt2);
    cudaGetSymbolAddress((void**)&w2,   g_w2);
    cudaGetSymbolAddress((void**)&s2p,  g_s2);
    cudaGetSymbolAddress((void**)&kg,   g_kg);
    cudaGetSymbolAddress((void**)&vpt,  g_vpt);
    cudaGetSymbolAddress((void**)&s,    g_s);
    cudaGetSymbolAddress((void**)&p,    g_p);

    static cudaStream_t s1 = nullptr, s2 = nullptr, s3 = nullptr;
    static cudaEvent_t eFork, eRqk, eRv, eGt2, eS2, eVpt, eDone;
    if (!s1) {
        cudaStreamCreateWithFlags(&s1, cudaStreamNonBlocking);
        cudaStreamCreateWithFlags(&s2, cudaStreamNonBlocking);
        cudaStreamCreateWithFlags(&s3, cudaStreamNonBlocking);
        cudaEventCreateWithFlags(&eFork, cudaEventDisableTiming);
        cudaEventCreateWithFlags(&eRqk,  cudaEventDisableTiming);
        cudaEventCreateWithFlags(&eRv,   cudaEventDisableTiming);
        cudaEventCreateWithFlags(&eGt2,  cudaEventDisableTiming);
        cudaEventCreateWithFlags(&eS2,   cudaEventDisableTiming);
        cudaEventCreateWithFlags(&eVpt,  cudaEventDisableTiming);
        cudaEventCreateWithFlags(&eDone, cudaEventDisableTiming);
        cudaFuncSetAttribute(hgemm_nt, cudaFuncAttributeMaxDynamicSharedMemorySize, SMEM_BYTES);
    }

    const int nq4 = BATCH * NQ * DIM / 4;
    const int nk4 = BATCH * LSEQ * DIM / 4;
    const float SCALE = 0.03608439182435161f;

    const size_t oRQ  = (size_t)HB * NQ * DIM;
    const size_t oRK  = (size_t)HB * LSEQ * DIM;
    const size_t oKG  = (size_t)HB * LSEQ * DIM;
    const size_t oS   = (size_t)HB * NQ * LSEQ;
    const size_t oS2  = (size_t)HB * LSEQ;
    const size_t oVPT = (size_t)HB * DIM * LSEQ;
    const size_t oOUT = (size_t)HB * NQ * DIM;

    // ---- fork ----
    cudaEventRecord(eFork, 0);
    cudaStreamWaitEvent(s1, eFork, 0);
    cudaStreamWaitEvent(s2, eFork, 0);
    cudaStreamWaitEvent(s3, eFork, 0);

    // s0: round q + k (both needed on the S critical path)
    round3_h<<<(nq4 + nk4) / 256, 256, 0, 0>>>(q, rq, k, rk, k, rk, nq4, nk4);
    cudaEventRecord(eRqk, 0);

    // s1: weight transpose/round -> gt2 = qw^T-major x kw^T-major
    //     gt2[c][c'] = sum_d qw[d,c] kw[d,c']  (A=rwqt, B=rwkt)
    transpose_round<<<dim3(24, 24, 3), dim3(32, 8), 0, s1>>>(q_w, rwqt, k_w, rwkt, v_w, rwv);
    hgemm_nt<<<dim3(DIM / 128, DIM / 128, 1), 256, SMEM_BYTES, s1>>>(
        rwqt, rwkt, nullptr, gt2, DIM, DIM, 0, 0, 0, 0, 1);
    cudaEventRecord(eGt2, s1);

    // s2: w2 -> round v -> (after rk) s2
    compute_w2<<<DIM / 32, 256, 0, s2>>>(k_w, q_b, w2);
    round3_h<<<nk4 / 256, 256, 0, s2>>>(v, rv, v, rv, v, rv, nk4, 0);
    cudaEventRecord(eRv, s2);
    cudaStreamWaitEvent(s2, eRqk, 0);
    compute_s2<<<(BATCH * LSEQ) / 8, 256, 0, s2>>>(rk, w2, s2p);
    cudaEventRecord(eS2, s2);

    // s1: vpt (needs rv)
    cudaStreamWaitEvent(s1, eRv, 0);
    hgemm_nt<<<dim3(LSEQ / 128, DIM / 128, BATCH), 256, SMEM_BYTES, s1>>>(
        rwv, rv, v_b, vpt, DIM, LSEQ,
        0, (long)LSEQ * DIM, (long)DIM * LSEQ, 2, 1);
    cudaEventRecord(eVpt, s1);

    // ---- batch halves: s0 -> b 0..15, s3 -> b 16..31 ----

    // kG halves: kG[l,c] = sum_c' rk[l,c'] gt2[c][c']  (M=8192, N=768 each)
    cudaStreamWaitEvent(0, eGt2, 0);
    hgemm_nt<<<dim3(DIM / 128, (HB * LSEQ) / 128, 1), 256, SMEM_BYTES, 0>>>(
        rk, gt2, nullptr, kg, DIM, DIM, 0, 0, 0, 0, 1);
    cudaStreamWaitEvent(s3, eGt2, 0);
    cudaStreamWaitEvent(s3, eRqk, 0);
    hgemm_nt<<<dim3(DIM / 128, (HB * LSEQ) / 128, 1), 256, SMEM_BYTES, s3>>>(
        rk + oRK, gt2, nullptr, kg + oKG, DIM, DIM, 0, 0, 0, 0, 1);

    // S halves: S[b] = rq[b] @ kG[b]^T  (M=1024, N=512, K=768)
    hgemm_nt<<<dim3(LSEQ / 128, NQ / 128, HB), 256, SMEM_BYTES, 0>>>(
        rq, kg, nullptr, s, DIM, LSEQ,
        (long)NQ * DIM, (long)LSEQ * DIM, (long)NQ * LSEQ, 0, 0);
    hgemm_nt<<<dim3(LSEQ / 128, NQ / 128, HB), 256, SMEM_BYTES, s3>>>(
        rq + oRQ, kg + oKG, nullptr, s + oS, DIM, LSEQ,
        (long)NQ * DIM, (long)LSEQ * DIM, (long)NQ * LSEQ, 0, 0);

    // softmax halves -> fp16 probs
    cudaStreamWaitEvent(0, eS2, 0);
    softmax_rows<<<(HB * NQ) / 8, 256, 0, 0>>>(s, s2p, p, SCALE);
    cudaStreamWaitEvent(s3, eS2, 0);
    softmax_rows<<<(HB * NQ) / 8, 256, 0, s3>>>(s + oS, s2p + oS2, p + oS, SCALE);

    // out halves (need vpt)
    cudaStreamWaitEvent(0, eVpt, 0);
    hgemm_nt<<<dim3(DIM / 128, NQ / 128, HB), 256, SMEM_BYTES, 0>>>(
        p, vpt, nullptr, out, LSEQ, DIM,
        (long)NQ * LSEQ, (long)DIM * LSEQ, (long)NQ * DIM, 0, 0);
    cudaStreamWaitEvent(s3, eVpt, 0);
    hgemm_nt<<<dim3(DIM / 128, NQ / 128, HB), 256, SMEM_BYTES, s3>>>(
        p + oS, vpt + oVPT, nullptr, out + oOUT, LSEQ, DIM,
        (long)NQ * LSEQ, (long)DIM * LSEQ, (long)NQ * DIM, 0, 0);

    // ---- join ----
    cudaEventRecord(eDone, s3);
    cudaStreamWaitEvent(0, eDone, 0);
}